// round 13
// baseline (speedup 1.0000x reference)
#include <cuda_runtime.h>
#include <cuda_bf16.h>
#include <cstdint>

#define B_ 2
#define N_ 2048
#define C_ 1024
#define H_ 16
#define D_ 64

// ------------------------- scratch (__device__ globals) ----------------------
__device__ float g_Q[(size_t)B_*H_*N_*D_];   // tf32-rounded, pre-scaled by 1/8
__device__ float g_K[(size_t)B_*H_*N_*D_];   // tf32-rounded
__device__ float g_V[(size_t)B_*H_*N_*D_];   // tf32-rounded

__device__ __nv_bfloat16 g_Xs[2u*4096u*1024u];    // x   split: hi plane, lo plane
__device__ __nv_bfloat16 g_Cs[2u*4096u*1024u];    // ctx split
__device__ __nv_bfloat16 g_Os[2u*4096u*1024u];    // attn-out split (written by attn)
__device__ __nv_bfloat16 g_Ws[4u*2u*1024u*1024u]; // 4 weights x (hi, lo)

// ------------------------------- PTX helpers --------------------------------
__device__ __forceinline__ unsigned f2tf32(float f) {
    unsigned o; asm("cvt.rna.tf32.f32 %0, %1;" : "=r"(o) : "f"(f)); return o;
}
__device__ __forceinline__ void mma_tf32(float c[4], const unsigned a[4],
                                         unsigned b0, unsigned b1) {
    asm volatile("mma.sync.aligned.m16n8k8.row.col.f32.tf32.tf32.f32 "
        "{%0,%1,%2,%3}, {%4,%5,%6,%7}, {%8,%9}, {%0,%1,%2,%3};"
        : "+f"(c[0]), "+f"(c[1]), "+f"(c[2]), "+f"(c[3])
        : "r"(a[0]), "r"(a[1]), "r"(a[2]), "r"(a[3]), "r"(b0), "r"(b1));
}
__device__ __forceinline__ void mma_bf16(float c[4], const unsigned a[4],
                                         unsigned b0, unsigned b1) {
    asm volatile("mma.sync.aligned.m16n8k16.row.col.f32.bf16.bf16.f32 "
        "{%0,%1,%2,%3}, {%4,%5,%6,%7}, {%8,%9}, {%0,%1,%2,%3};"
        : "+f"(c[0]), "+f"(c[1]), "+f"(c[2]), "+f"(c[3])
        : "r"(a[0]), "r"(a[1]), "r"(a[2]), "r"(a[3]), "r"(b0), "r"(b1));
}
__device__ __forceinline__ void ldmx4(unsigned addr, unsigned r[4]) {
    asm volatile("ldmatrix.sync.aligned.m8n8.x4.shared.b16 {%0,%1,%2,%3}, [%4];"
        : "=r"(r[0]), "=r"(r[1]), "=r"(r[2]), "=r"(r[3]) : "r"(addr));
}
__device__ __forceinline__ void cp16(unsigned dst, const void* src) {
    asm volatile("cp.async.cg.shared.global [%0], [%1], 16;" :: "r"(dst), "l"(src));
}
#define CP_COMMIT() asm volatile("cp.async.commit_group;")
#define CP_WAIT1()  asm volatile("cp.async.wait_group 1;")
#define CP_WAIT0()  asm volatile("cp.async.wait_group 0;")
__device__ __forceinline__ unsigned s_u32(const void* p) {
    return (unsigned)__cvta_generic_to_shared(p);
}

// ----------------------- merged bf16 hi/lo split kernel ---------------------
__global__ __launch_bounds__(256)
void split_all_kernel(const float* __restrict__ x, const float* __restrict__ ctx,
                      const float* __restrict__ Wq, const float* __restrict__ Wk,
                      const float* __restrict__ Wv, const float* __restrict__ Wo,
                      __nv_bfloat16* __restrict__ xs, __nv_bfloat16* __restrict__ cs,
                      __nv_bfloat16* __restrict__ ws)
{
    int blk = blockIdx.x;
    const float* src;
    __nv_bfloat16* dst;
    int n4;
    if (blk < 4096)      { src = x;   dst = xs; n4 = 1048576; }
    else if (blk < 8192) { src = ctx; dst = cs; n4 = 1048576; blk -= 4096; }
    else {
        int w = (blk - 8192) >> 10;
        blk = (blk - 8192) & 1023;
        n4 = 262144;
        src = (w == 0) ? Wq : (w == 1) ? Wk : (w == 2) ? Wv : Wo;
        dst = ws + (size_t)w * 2097152u;
    }
    int i = blk * 256 + threadIdx.x;
    if (i >= n4) return;
    float4 v = reinterpret_cast<const float4*>(src)[i];
    __nv_bfloat16 h0 = __float2bfloat16_rn(v.x);
    __nv_bfloat16 h1 = __float2bfloat16_rn(v.y);
    __nv_bfloat16 h2 = __float2bfloat16_rn(v.z);
    __nv_bfloat16 h3 = __float2bfloat16_rn(v.w);
    __nv_bfloat16 l0 = __float2bfloat16_rn(v.x - __bfloat162float(h0));
    __nv_bfloat16 l1 = __float2bfloat16_rn(v.y - __bfloat162float(h1));
    __nv_bfloat16 l2 = __float2bfloat16_rn(v.z - __bfloat162float(h2));
    __nv_bfloat16 l3 = __float2bfloat16_rn(v.w - __bfloat162float(h3));
    __nv_bfloat162* hi2 = reinterpret_cast<__nv_bfloat162*>(dst);
    __nv_bfloat162* lo2 = reinterpret_cast<__nv_bfloat162*>(dst + (size_t)n4 * 4);
    hi2[2*i+0] = __halves2bfloat162(h0, h1);
    hi2[2*i+1] = __halves2bfloat162(h2, h3);
    lo2[2*i+0] = __halves2bfloat162(l0, l1);
    lo2[2*i+1] = __halves2bfloat162(l2, l3);
}

// ---------------------- bf16 3-term split GEMM (proj) -----------------------
// out[M=4096, 1024] = A @ W^T + bias.  A/W pre-split into bf16 hi/lo planes.
// Block: 256 thr (8 warps: 4m x 2n), tile 128x64, BK=32, cp.async 2 stages.
// smem per stage (uint words): A [2pl][128][20] = 5120, B [2pl][64][20] = 2560.
// Fragment loads via ldmatrix.x4 (8 per k16-step instead of 32 scalar LDS):
// row stride 80B -> 8-row address set {0,80,32,112,64,16,96,48} mod 128, no
// bank conflicts. One B x4 yields two n8 fragments (r0/r2 even, r1/r3 odd).
struct ProjArgs {
    const __nv_bfloat16* A[3];
    const __nv_bfloat16* Wp[3];
    const float* bias[3];
    float* out[3];
    float scale[3];
};

template<bool HEAD_MAJOR, bool ROUND>
__global__ __launch_bounds__(256, 2)
void proj_bf16_kernel(ProjArgs args)
{
    extern __shared__ __align__(16) unsigned sm32[];
    const int z = blockIdx.z;
    const __nv_bfloat16* A = args.A[z];
    const __nv_bfloat16* W = args.Wp[z];
    const float* bias      = args.bias[z];
    float* out             = args.out[z];
    const float oscale     = args.scale[z];

    const int tid  = threadIdx.x;
    const int lane = tid & 31, warp = tid >> 5;
    const int wm   = (warp >> 1) * 32, wn = (warp & 1) * 32;
    const int g    = lane >> 2, j = lane & 3;
    const int m0   = blockIdx.y * 128, j0 = blockIdx.x * 64;

    const __nv_bfloat16* Apl0 = A;
    const __nv_bfloat16* Apl1 = A + (size_t)4096 * 1024;
    const __nv_bfloat16* Wpl0 = W;
    const __nv_bfloat16* Wpl1 = W + (size_t)1024 * 1024;
    const unsigned sbase = s_u32(sm32);

    float acc[2][4][4];
    #pragma unroll
    for (int a = 0; a < 2; a++)
        #pragma unroll
        for (int b = 0; b < 4; b++)
            #pragma unroll
            for (int c = 0; c < 4; c++) acc[a][b][c] = 0.0f;

    auto issue_tile = [&](int kt, int stg) {
        unsigned base = sbase + (unsigned)stg * 7680u * 4u;
        #pragma unroll
        for (int i = 0; i < 4; i++) {                 // A: 1024 x 16B
            int c  = tid + i * 256;
            int pl = c >> 9, rem = c & 511, r = rem >> 2, q = rem & 3;
            const __nv_bfloat16* src = (pl ? Apl1 : Apl0) +
                (size_t)(m0 + r) * 1024 + kt + q * 8;
            cp16(base + (unsigned)(pl * 2560 + r * 20 + q * 4) * 4u, src);
        }
        #pragma unroll
        for (int i = 0; i < 2; i++) {                 // B: 512 x 16B
            int c  = tid + i * 256;
            int pl = c >> 8, rem = c & 255, r = rem >> 2, q = rem & 3;
            const __nv_bfloat16* src = (pl ? Wpl1 : Wpl0) +
                (size_t)(j0 + r) * 1024 + kt + q * 8;
            cp16(base + (unsigned)(5120 + pl * 1280 + r * 20 + q * 4) * 4u, src);
        }
    };

    issue_tile(0, 0);
    CP_COMMIT();

    // ldmatrix per-thread base offsets (bytes)
    const unsigned lrow = (unsigned)(lane & 15);
    const unsigned lkb  = (unsigned)(lane >> 4) * 16u;   // k-half: +4 words = 16B
    const unsigned aoff = (unsigned)((wm + lrow) * 20) * 4u + lkb;       // A hi, mf0
    const unsigned boff = (unsigned)((5120 + (wn + lrow) * 20)) * 4u + lkb; // B hi, pair0

    for (int t = 0; t < 32; t++) {
        if (t + 1 < 32) { issue_tile((t + 1) * 32, (t + 1) & 1); CP_COMMIT(); CP_WAIT1(); }
        else            { CP_WAIT0(); }
        __syncthreads();

        const unsigned sb = sbase + (unsigned)(t & 1) * 7680u * 4u;
        #pragma unroll
        for (int ks = 0; ks < 2; ks++) {
            const unsigned ko = (unsigned)(ks * 8) * 4u;  // k16-step: +8 words
            unsigned ah0[4], ah1[4], al0[4], al1[4];
            unsigned bh0[4], bh1[4], bl0[4], bl1[4];
            ldmx4(sb + aoff + ko,                  ah0);  // A hi rows wm+0..15
            ldmx4(sb + aoff + 1280u + ko,          ah1);  // A hi rows wm+16..31
            ldmx4(sb + aoff + 10240u + ko,         al0);  // A lo rows wm+0..15
            ldmx4(sb + aoff + 11520u + ko,         al1);  // A lo rows wm+16..31
            ldmx4(sb + boff + ko,                  bh0);  // B hi n wn+0..15 (nf0,nf1)
            ldmx4(sb + boff + 1280u + ko,          bh1);  // B hi n wn+16..31 (nf2,nf3)
            ldmx4(sb + boff + 5120u + ko,          bl0);  // B lo n wn+0..15
            ldmx4(sb + boff + 6400u + ko,          bl1);  // B lo n wn+16..31

            // hh terms
            mma_bf16(acc[0][0], ah0, bh0[0], bh0[2]);
            mma_bf16(acc[0][1], ah0, bh0[1], bh0[3]);
            mma_bf16(acc[0][2], ah0, bh1[0], bh1[2]);
            mma_bf16(acc[0][3], ah0, bh1[1], bh1[3]);
            mma_bf16(acc[1][0], ah1, bh0[0], bh0[2]);
            mma_bf16(acc[1][1], ah1, bh0[1], bh0[3]);
            mma_bf16(acc[1][2], ah1, bh1[0], bh1[2]);
            mma_bf16(acc[1][3], ah1, bh1[1], bh1[3]);
            // hl terms
            mma_bf16(acc[0][0], ah0, bl0[0], bl0[2]);
            mma_bf16(acc[0][1], ah0, bl0[1], bl0[3]);
            mma_bf16(acc[0][2], ah0, bl1[0], bl1[2]);
            mma_bf16(acc[0][3], ah0, bl1[1], bl1[3]);
            mma_bf16(acc[1][0], ah1, bl0[0], bl0[2]);
            mma_bf16(acc[1][1], ah1, bl0[1], bl0[3]);
            mma_bf16(acc[1][2], ah1, bl1[0], bl1[2]);
            mma_bf16(acc[1][3], ah1, bl1[1], bl1[3]);
            // lh terms
            mma_bf16(acc[0][0], al0, bh0[0], bh0[2]);
            mma_bf16(acc[0][1], al0, bh0[1], bh0[3]);
            mma_bf16(acc[0][2], al0, bh1[0], bh1[2]);
            mma_bf16(acc[0][3], al0, bh1[1], bh1[3]);
            mma_bf16(acc[1][0], al1, bh0[0], bh0[2]);
            mma_bf16(acc[1][1], al1, bh0[1], bh0[3]);
            mma_bf16(acc[1][2], al1, bh1[0], bh1[2]);
            mma_bf16(acc[1][3], al1, bh1[1], bh1[3]);
        }
        __syncthreads();
    }

    #pragma unroll
    for (int mf = 0; mf < 2; mf++) {
        #pragma unroll
        for (int e = 0; e < 2; e++) {
            int row = m0 + wm + mf * 16 + g + e * 8;
            #pragma unroll
            for (int nf = 0; nf < 4; nf++) {
                int col = j0 + wn + nf * 8 + 2 * j;
                float v0 = (acc[mf][nf][e * 2 + 0] + bias[col])     * oscale;
                float v1 = (acc[mf][nf][e * 2 + 1] + bias[col + 1]) * oscale;
                if (ROUND) {
                    v0 = __uint_as_float(f2tf32(v0));
                    v1 = __uint_as_float(f2tf32(v1));
                }
                float2 val = make_float2(v0, v1);
                if (HEAD_MAJOR) {
                    int bb = row >> 11, n = row & (N_ - 1);
                    int d  = col - j0;
                    *reinterpret_cast<float2*>(
                        &out[(((size_t)bb * H_ + blockIdx.x) * N_ + n) * 64 + d]) = val;
                } else {
                    *reinterpret_cast<float2*>(&out[(size_t)row * 1024 + col]) = val;
                }
            }
        }
    }
}

// --------------------- register-resident flash attention --------------------
// (unchanged from round 11 — proven at rel_err 3.0e-4)
__global__ __launch_bounds__(128, 2)
void attn_kernel(const float* __restrict__ Qg, const float* __restrict__ Kg,
                 const float* __restrict__ Vg, const float* __restrict__ bias,
                 __nv_bfloat16* __restrict__ Ohi)
{
    extern __shared__ __align__(16) float sf[];
    const int tid  = threadIdx.x;
    const int lane = tid & 31, warp = tid >> 5;
    const int g    = lane >> 2, j = lane & 3;
    const int q0   = blockIdx.x * 64, h = blockIdx.y, b = blockIdx.z;
    const size_t bh = ((size_t)b * H_ + h) * N_;
    const int wq   = warp * 16;
    float* Psw = sf + 17920 + warp * 1088;
    const unsigned sbase = s_u32(sf);
    __nv_bfloat16* Olo = Ohi + (size_t)4096 * 1024;

    unsigned qa[8][4];
    {
        const float* q0p = Qg + (bh + q0 + wq + g) * 64;
        const float* q1p = q0p + 8 * 64;
        #pragma unroll
        for (int dk = 0; dk < 8; dk++) {
            qa[dk][0] = __float_as_uint(q0p[dk * 8 + j]);
            qa[dk][1] = __float_as_uint(q1p[dk * 8 + j]);
            qa[dk][2] = __float_as_uint(q0p[dk * 8 + j + 4]);
            qa[dk][3] = __float_as_uint(q1p[dk * 8 + j + 4]);
        }
    }

    float Oa[8][4];
    #pragma unroll
    for (int nb = 0; nb < 8; nb++)
        #pragma unroll
        for (int e = 0; e < 4; e++) Oa[nb][e] = 0.0f;
    float m0r = -1e30f, m1r = -1e30f, l0 = 0.0f, l1 = 0.0f;

    auto issue_kv = [&](int k0, int stg) {
        unsigned kbase = sbase + (unsigned)(stg * 4352) * 4u;
        unsigned vbase = sbase + (unsigned)(8704 + stg * 4608) * 4u;
        const float* Kp = Kg + (bh + k0) * 64;
        const float* Vp = Vg + (bh + k0) * 64;
        #pragma unroll
        for (int i = 0; i < 8; i++) {
            int c = tid + i * 128;
            int r = c >> 4, cc = (c & 15) * 4;
            cp16(kbase + (unsigned)(r * 68 + cc) * 4u, Kp + r * 64 + cc);
            cp16(vbase + (unsigned)(r * 72 + cc) * 4u, Vp + r * 64 + cc);
        }
    };

    issue_kv(0, 0);
    CP_COMMIT();

    const float* bb0 = bias + ((size_t)h * N_ + q0 + wq + g) * N_;
    const float* bb1 = bb0 + (size_t)8 * N_;

    for (int t = 0; t < 32; t++) {
        if (t + 1 < 32) { issue_kv((t + 1) * 64, (t + 1) & 1); CP_COMMIT(); CP_WAIT1(); }
        else            { CP_WAIT0(); }
        __syncthreads();

        const float* Ks = sf + (t & 1) * 4352;
        const float* Vs = sf + 8704 + (t & 1) * 4608;
        const int kcol = t * 64;

        float2 bt0[8], bt1[8];
        #pragma unroll
        for (int nb = 0; nb < 8; nb++) {
            bt0[nb] = *reinterpret_cast<const float2*>(bb0 + kcol + nb * 8 + 2 * j);
            bt1[nb] = *reinterpret_cast<const float2*>(bb1 + kcol + nb * 8 + 2 * j);
        }

        float sa[8][4];
        #pragma unroll
        for (int nb = 0; nb < 8; nb++)
            #pragma unroll
            for (int e = 0; e < 4; e++) sa[nb][e] = 0.0f;
        #pragma unroll
        for (int dk = 0; dk < 8; dk++)
            #pragma unroll
            for (int nb = 0; nb < 8; nb++) {
                const float* kp = Ks + (nb * 8 + g) * 68 + dk * 8 + j;
                mma_tf32(sa[nb], qa[dk], __float_as_uint(kp[0]),
                                         __float_as_uint(kp[4]));
            }

        float mx0 = -1e30f, mx1 = -1e30f;
        #pragma unroll
        for (int nb = 0; nb < 8; nb++) {
            sa[nb][0] += bt0[nb].x; sa[nb][1] += bt0[nb].y;
            sa[nb][2] += bt1[nb].x; sa[nb][3] += bt1[nb].y;
            mx0 = fmaxf(mx0, fmaxf(sa[nb][0], sa[nb][1]));
            mx1 = fmaxf(mx1, fmaxf(sa[nb][2], sa[nb][3]));
        }
        mx0 = fmaxf(mx0, __shfl_xor_sync(0xffffffffu, mx0, 1));
        mx0 = fmaxf(mx0, __shfl_xor_sync(0xffffffffu, mx0, 2));
        mx1 = fmaxf(mx1, __shfl_xor_sync(0xffffffffu, mx1, 1));
        mx1 = fmaxf(mx1, __shfl_xor_sync(0xffffffffu, mx1, 2));
        float mn0 = fmaxf(m0r, mx0), mn1 = fmaxf(m1r, mx1);
        float al0 = __expf(m0r - mn0), al1 = __expf(m1r - mn1);
        m0r = mn0; m1r = mn1;

        __syncwarp();
        float s0 = 0.0f, s1 = 0.0f;
        #pragma unroll
        for (int nb = 0; nb < 8; nb++) {
            float p0 = __expf(sa[nb][0] - mn0);
            float p1 = __expf(sa[nb][1] - mn0);
            float p2 = __expf(sa[nb][2] - mn1);
            float p3 = __expf(sa[nb][3] - mn1);
            s0 += p0 + p1; s1 += p2 + p3;
            Psw[g * 68 + nb * 8 + 2 * j]           = __uint_as_float(f2tf32(p0));
            Psw[g * 68 + nb * 8 + 2 * j + 1]       = __uint_as_float(f2tf32(p1));
            Psw[(g + 8) * 68 + nb * 8 + 2 * j]     = __uint_as_float(f2tf32(p2));
            Psw[(g + 8) * 68 + nb * 8 + 2 * j + 1] = __uint_as_float(f2tf32(p3));
            Oa[nb][0] *= al0; Oa[nb][1] *= al0;
            Oa[nb][2] *= al1; Oa[nb][3] *= al1;
        }
        s0 += __shfl_xor_sync(0xffffffffu, s0, 1);
        s0 += __shfl_xor_sync(0xffffffffu, s0, 2);
        s1 += __shfl_xor_sync(0xffffffffu, s1, 1);
        s1 += __shfl_xor_sync(0xffffffffu, s1, 2);
        l0 = l0 * al0 + s0;
        l1 = l1 * al1 + s1;
        __syncwarp();

        #pragma unroll
        for (int kk = 0; kk < 8; kk++) {
            unsigned pa[4];
            pa[0] = __float_as_uint(Psw[g * 68 + kk * 8 + j]);
            pa[1] = __float_as_uint(Psw[(g + 8) * 68 + kk * 8 + j]);
            pa[2] = __float_as_uint(Psw[g * 68 + kk * 8 + j + 4]);
            pa[3] = __float_as_uint(Psw[(g + 8) * 68 + kk * 8 + j + 4]);
            #pragma unroll
            for (int nb = 0; nb < 8; nb++) {
                const float* vp = Vs + (kk * 8 + j) * 72 + nb * 8 + g;
                mma_tf32(Oa[nb], pa, __float_as_uint(vp[0]),
                                     __float_as_uint(vp[4 * 72]));
            }
        }
        __syncthreads();
    }

    const float li0 = 1.0f / l0, li1 = 1.0f / l1;
    const size_t row0 = ((size_t)b * N_ + q0 + wq + g) * 1024;
    const size_t row1 = row0 + (size_t)8 * 1024;
    #pragma unroll
    for (int nb = 0; nb < 8; nb++) {
        const size_t c = (size_t)h * 64 + nb * 8 + 2 * j;
        float v0 = Oa[nb][0] * li0, v1 = Oa[nb][1] * li0;
        float v2 = Oa[nb][2] * li1, v3 = Oa[nb][3] * li1;
        __nv_bfloat16 h0 = __float2bfloat16_rn(v0);
        __nv_bfloat16 h1 = __float2bfloat16_rn(v1);
        __nv_bfloat16 h2 = __float2bfloat16_rn(v2);
        __nv_bfloat16 h3 = __float2bfloat16_rn(v3);
        __nv_bfloat16 e0 = __float2bfloat16_rn(v0 - __bfloat162float(h0));
        __nv_bfloat16 e1 = __float2bfloat16_rn(v1 - __bfloat162float(h1));
        __nv_bfloat16 e2 = __float2bfloat16_rn(v2 - __bfloat162float(h2));
        __nv_bfloat16 e3 = __float2bfloat16_rn(v3 - __bfloat162float(h3));
        *reinterpret_cast<__nv_bfloat162*>(Ohi + row0 + c) = __halves2bfloat162(h0, h1);
        *reinterpret_cast<__nv_bfloat162*>(Ohi + row1 + c) = __halves2bfloat162(h2, h3);
        *reinterpret_cast<__nv_bfloat162*>(Olo + row0 + c) = __halves2bfloat162(e0, e1);
        *reinterpret_cast<__nv_bfloat162*>(Olo + row1 + c) = __halves2bfloat162(e2, e3);
    }
}

// --------------------------------- launcher ---------------------------------
extern "C" void kernel_launch(void* const* d_in, const int* in_sizes, int n_in,
                              void* d_out, int out_size)
{
    (void)in_sizes; (void)n_in; (void)out_size;
    const float* x    = (const float*)d_in[0];
    const float* ctx  = (const float*)d_in[1];
    const float* bias = (const float*)d_in[2];
    const float* Wq   = (const float*)d_in[3];
    const float* bq   = (const float*)d_in[4];
    const float* Wk   = (const float*)d_in[5];
    const float* bk   = (const float*)d_in[6];
    const float* Wv   = (const float*)d_in[7];
    const float* bv   = (const float*)d_in[8];
    const float* Wo   = (const float*)d_in[9];
    const float* bo   = (const float*)d_in[10];
    float* out = (float*)d_out;

    float *qp, *kp, *vp;
    __nv_bfloat16 *xs, *cs, *os, *ws;
    cudaGetSymbolAddress((void**)&qp, g_Q);
    cudaGetSymbolAddress((void**)&kp, g_K);
    cudaGetSymbolAddress((void**)&vp, g_V);
    cudaGetSymbolAddress((void**)&xs, g_Xs);
    cudaGetSymbolAddress((void**)&cs, g_Cs);
    cudaGetSymbolAddress((void**)&os, g_Os);
    cudaGetSymbolAddress((void**)&ws, g_Ws);

    const int proj_smem = 7680 * 2 * 4;   // 61,440 B
    const int attn_smem = 22272 * 4;      // 89,088 B
    cudaFuncSetAttribute(proj_bf16_kernel<true , true >,
        cudaFuncAttributeMaxDynamicSharedMemorySize, proj_smem);
    cudaFuncSetAttribute(proj_bf16_kernel<false, false>,
        cudaFuncAttributeMaxDynamicSharedMemorySize, proj_smem);
    cudaFuncSetAttribute(attn_kernel,
        cudaFuncAttributeMaxDynamicSharedMemorySize, attn_smem);
    cudaFuncSetAttribute(proj_bf16_kernel<true , true >,
        cudaFuncAttributePreferredSharedMemoryCarveout, 100);
    cudaFuncSetAttribute(proj_bf16_kernel<false, false>,
        cudaFuncAttributePreferredSharedMemoryCarveout, 100);
    cudaFuncSetAttribute(attn_kernel,
        cudaFuncAttributePreferredSharedMemoryCarveout, 100);

    const size_t WPITCH = (size_t)2 * 1024 * 1024;  // hi+lo plane per weight

    // 1) all splits in one launch
    split_all_kernel<<<12288, 256>>>(x, ctx, Wq, Wk, Wv, Wo, xs, cs, ws);

    // 2) merged Q/K/V projections (gridDim.z = 3)
    ProjArgs pa;
    pa.A[0] = xs; pa.Wp[0] = ws + 0 * WPITCH; pa.bias[0] = bq; pa.out[0] = qp; pa.scale[0] = 0.125f;
    pa.A[1] = cs; pa.Wp[1] = ws + 1 * WPITCH; pa.bias[1] = bk; pa.out[1] = kp; pa.scale[1] = 1.0f;
    pa.A[2] = cs; pa.Wp[2] = ws + 2 * WPITCH; pa.bias[2] = bv; pa.out[2] = vp; pa.scale[2] = 1.0f;
    dim3 gp(16, 32, 3);   // (C/64, 4096/128, QKV)
    proj_bf16_kernel<true , true ><<<gp, 256, proj_smem>>>(pa);

    // 3) attention (writes bf16 split planes directly)
    dim3 ga(N_ / 64, H_, B_);   // (32, 16, 2)
    attn_kernel<<<ga, 128, attn_smem>>>(qp, kp, vp, bias, os);

    // 4) output projection
    ProjArgs po;
    po.A[0] = os; po.Wp[0] = ws + 3 * WPITCH; po.bias[0] = bo; po.out[0] = out; po.scale[0] = 1.0f;
    po.A[1] = po.A[0]; po.Wp[1] = po.Wp[0]; po.bias[1] = po.bias[0]; po.out[1] = po.out[0]; po.scale[1] = 1.0f;
    po.A[2] = po.A[0]; po.Wp[2] = po.Wp[0]; po.bias[2] = po.bias[0]; po.out[2] = po.out[0]; po.scale[2] = 1.0f;
    dim3 go(16, 32, 1);
    proj_bf16_kernel<false, false><<<go, 256, proj_smem>>>(po);
}

// round 14
// speedup vs baseline: 1.0003x; 1.0003x over previous
#include <cuda_runtime.h>
#include <cuda_bf16.h>
#include <cstdint>

#define B_ 2
#define N_ 2048
#define C_ 1024
#define H_ 16
#define D_ 64

// ------------------------- scratch (__device__ globals) ----------------------
__device__ float g_Q[(size_t)B_*H_*N_*D_];   // tf32-rounded, pre-scaled by 1/8
__device__ float g_K[(size_t)B_*H_*N_*D_];   // tf32-rounded
__device__ float g_V[(size_t)B_*H_*N_*D_];   // tf32-rounded

__device__ __nv_bfloat16 g_Xs[2u*4096u*1024u];    // x   split: hi plane, lo plane
__device__ __nv_bfloat16 g_Cs[2u*4096u*1024u];    // ctx split
__device__ __nv_bfloat16 g_Os[2u*4096u*1024u];    // attn-out split (written by attn)
__device__ __nv_bfloat16 g_Ws[4u*2u*1024u*1024u]; // 4 weights x (hi, lo)

// ------------------------------- PTX helpers --------------------------------
__device__ __forceinline__ unsigned f2tf32(float f) {
    unsigned o; asm("cvt.rna.tf32.f32 %0, %1;" : "=r"(o) : "f"(f)); return o;
}
__device__ __forceinline__ void mma_tf32(float c[4], const unsigned a[4],
                                         unsigned b0, unsigned b1) {
    asm volatile("mma.sync.aligned.m16n8k8.row.col.f32.tf32.tf32.f32 "
        "{%0,%1,%2,%3}, {%4,%5,%6,%7}, {%8,%9}, {%0,%1,%2,%3};"
        : "+f"(c[0]), "+f"(c[1]), "+f"(c[2]), "+f"(c[3])
        : "r"(a[0]), "r"(a[1]), "r"(a[2]), "r"(a[3]), "r"(b0), "r"(b1));
}
__device__ __forceinline__ void mma_bf16(float c[4], const unsigned a[4],
                                         unsigned b0, unsigned b1) {
    asm volatile("mma.sync.aligned.m16n8k16.row.col.f32.bf16.bf16.f32 "
        "{%0,%1,%2,%3}, {%4,%5,%6,%7}, {%8,%9}, {%0,%1,%2,%3};"
        : "+f"(c[0]), "+f"(c[1]), "+f"(c[2]), "+f"(c[3])
        : "r"(a[0]), "r"(a[1]), "r"(a[2]), "r"(a[3]), "r"(b0), "r"(b1));
}
__device__ __forceinline__ void ldmx4(unsigned addr, unsigned r[4]) {
    asm volatile("ldmatrix.sync.aligned.m8n8.x4.shared.b16 {%0,%1,%2,%3}, [%4];"
        : "=r"(r[0]), "=r"(r[1]), "=r"(r[2]), "=r"(r[3]) : "r"(addr));
}
__device__ __forceinline__ void cp16(unsigned dst, const void* src) {
    asm volatile("cp.async.cg.shared.global [%0], [%1], 16;" :: "r"(dst), "l"(src));
}
#define CP_COMMIT() asm volatile("cp.async.commit_group;")
#define CP_WAIT1()  asm volatile("cp.async.wait_group 1;")
#define CP_WAIT0()  asm volatile("cp.async.wait_group 0;")
__device__ __forceinline__ unsigned s_u32(const void* p) {
    return (unsigned)__cvta_generic_to_shared(p);
}

// ----------------------- merged bf16 hi/lo split kernel ---------------------
__global__ __launch_bounds__(256)
void split_all_kernel(const float* __restrict__ x, const float* __restrict__ ctx,
                      const float* __restrict__ Wq, const float* __restrict__ Wk,
                      const float* __restrict__ Wv, const float* __restrict__ Wo,
                      __nv_bfloat16* __restrict__ xs, __nv_bfloat16* __restrict__ cs,
                      __nv_bfloat16* __restrict__ ws)
{
    int blk = blockIdx.x;
    const float* src;
    __nv_bfloat16* dst;
    int n4;
    if (blk < 4096)      { src = x;   dst = xs; n4 = 1048576; }
    else if (blk < 8192) { src = ctx; dst = cs; n4 = 1048576; blk -= 4096; }
    else {
        int w = (blk - 8192) >> 10;
        blk = (blk - 8192) & 1023;
        n4 = 262144;
        src = (w == 0) ? Wq : (w == 1) ? Wk : (w == 2) ? Wv : Wo;
        dst = ws + (size_t)w * 2097152u;
    }
    int i = blk * 256 + threadIdx.x;
    if (i >= n4) return;
    float4 v = reinterpret_cast<const float4*>(src)[i];
    __nv_bfloat16 h0 = __float2bfloat16_rn(v.x);
    __nv_bfloat16 h1 = __float2bfloat16_rn(v.y);
    __nv_bfloat16 h2 = __float2bfloat16_rn(v.z);
    __nv_bfloat16 h3 = __float2bfloat16_rn(v.w);
    __nv_bfloat16 l0 = __float2bfloat16_rn(v.x - __bfloat162float(h0));
    __nv_bfloat16 l1 = __float2bfloat16_rn(v.y - __bfloat162float(h1));
    __nv_bfloat16 l2 = __float2bfloat16_rn(v.z - __bfloat162float(h2));
    __nv_bfloat16 l3 = __float2bfloat16_rn(v.w - __bfloat162float(h3));
    __nv_bfloat162* hi2 = reinterpret_cast<__nv_bfloat162*>(dst);
    __nv_bfloat162* lo2 = reinterpret_cast<__nv_bfloat162*>(dst + (size_t)n4 * 4);
    hi2[2*i+0] = __halves2bfloat162(h0, h1);
    hi2[2*i+1] = __halves2bfloat162(h2, h3);
    lo2[2*i+0] = __halves2bfloat162(l0, l1);
    lo2[2*i+1] = __halves2bfloat162(l2, l3);
}

// ---------------------- bf16 3-term split GEMM (proj) -----------------------
// Same structure as round 13 (ldmatrix fragment loads), but 3 CTAs/SM:
// smem 3x61440 = 184KB <= 228KB, regs capped at 85 by launch bounds.
struct ProjArgs {
    const __nv_bfloat16* A[3];
    const __nv_bfloat16* Wp[3];
    const float* bias[3];
    float* out[3];
    float scale[3];
};

template<bool HEAD_MAJOR, bool ROUND>
__global__ __launch_bounds__(256, 3)
void proj_bf16_kernel(ProjArgs args)
{
    extern __shared__ __align__(16) unsigned sm32[];
    const int z = blockIdx.z;
    const __nv_bfloat16* A = args.A[z];
    const __nv_bfloat16* W = args.Wp[z];
    const float* bias      = args.bias[z];
    float* out             = args.out[z];
    const float oscale     = args.scale[z];

    const int tid  = threadIdx.x;
    const int lane = tid & 31, warp = tid >> 5;
    const int wm   = (warp >> 1) * 32, wn = (warp & 1) * 32;
    const int g    = lane >> 2, j = lane & 3;
    const int m0   = blockIdx.y * 128, j0 = blockIdx.x * 64;

    const __nv_bfloat16* Apl0 = A;
    const __nv_bfloat16* Apl1 = A + (size_t)4096 * 1024;
    const __nv_bfloat16* Wpl0 = W;
    const __nv_bfloat16* Wpl1 = W + (size_t)1024 * 1024;
    const unsigned sbase = s_u32(sm32);

    float acc[2][4][4];
    #pragma unroll
    for (int a = 0; a < 2; a++)
        #pragma unroll
        for (int b = 0; b < 4; b++)
            #pragma unroll
            for (int c = 0; c < 4; c++) acc[a][b][c] = 0.0f;

    auto issue_tile = [&](int kt, int stg) {
        unsigned base = sbase + (unsigned)stg * 7680u * 4u;
        #pragma unroll
        for (int i = 0; i < 4; i++) {                 // A: 1024 x 16B
            int c  = tid + i * 256;
            int pl = c >> 9, rem = c & 511, r = rem >> 2, q = rem & 3;
            const __nv_bfloat16* src = (pl ? Apl1 : Apl0) +
                (size_t)(m0 + r) * 1024 + kt + q * 8;
            cp16(base + (unsigned)(pl * 2560 + r * 20 + q * 4) * 4u, src);
        }
        #pragma unroll
        for (int i = 0; i < 2; i++) {                 // B: 512 x 16B
            int c  = tid + i * 256;
            int pl = c >> 8, rem = c & 255, r = rem >> 2, q = rem & 3;
            const __nv_bfloat16* src = (pl ? Wpl1 : Wpl0) +
                (size_t)(j0 + r) * 1024 + kt + q * 8;
            cp16(base + (unsigned)(5120 + pl * 1280 + r * 20 + q * 4) * 4u, src);
        }
    };

    issue_tile(0, 0);
    CP_COMMIT();

    const unsigned lrow = (unsigned)(lane & 15);
    const unsigned lkb  = (unsigned)(lane >> 4) * 16u;
    const unsigned aoff = (unsigned)((wm + lrow) * 20) * 4u + lkb;
    const unsigned boff = (unsigned)((5120 + (wn + lrow) * 20)) * 4u + lkb;

    for (int t = 0; t < 32; t++) {
        if (t + 1 < 32) { issue_tile((t + 1) * 32, (t + 1) & 1); CP_COMMIT(); CP_WAIT1(); }
        else            { CP_WAIT0(); }
        __syncthreads();

        const unsigned sb = sbase + (unsigned)(t & 1) * 7680u * 4u;
        #pragma unroll
        for (int ks = 0; ks < 2; ks++) {
            const unsigned ko = (unsigned)(ks * 8) * 4u;
            unsigned ah0[4], ah1[4], al0[4], al1[4];
            unsigned bh0[4], bh1[4], bl0[4], bl1[4];
            ldmx4(sb + aoff + ko,          ah0);
            ldmx4(sb + aoff + 1280u + ko,  ah1);
            ldmx4(sb + aoff + 10240u + ko, al0);
            ldmx4(sb + aoff + 11520u + ko, al1);
            ldmx4(sb + boff + ko,          bh0);
            ldmx4(sb + boff + 1280u + ko,  bh1);
            ldmx4(sb + boff + 5120u + ko,  bl0);
            ldmx4(sb + boff + 6400u + ko,  bl1);

            mma_bf16(acc[0][0], ah0, bh0[0], bh0[2]);
            mma_bf16(acc[0][1], ah0, bh0[1], bh0[3]);
            mma_bf16(acc[0][2], ah0, bh1[0], bh1[2]);
            mma_bf16(acc[0][3], ah0, bh1[1], bh1[3]);
            mma_bf16(acc[1][0], ah1, bh0[0], bh0[2]);
            mma_bf16(acc[1][1], ah1, bh0[1], bh0[3]);
            mma_bf16(acc[1][2], ah1, bh1[0], bh1[2]);
            mma_bf16(acc[1][3], ah1, bh1[1], bh1[3]);

            mma_bf16(acc[0][0], ah0, bl0[0], bl0[2]);
            mma_bf16(acc[0][1], ah0, bl0[1], bl0[3]);
            mma_bf16(acc[0][2], ah0, bl1[0], bl1[2]);
            mma_bf16(acc[0][3], ah0, bl1[1], bl1[3]);
            mma_bf16(acc[1][0], ah1, bl0[0], bl0[2]);
            mma_bf16(acc[1][1], ah1, bl0[1], bl0[3]);
            mma_bf16(acc[1][2], ah1, bl1[0], bl1[2]);
            mma_bf16(acc[1][3], ah1, bl1[1], bl1[3]);

            mma_bf16(acc[0][0], al0, bh0[0], bh0[2]);
            mma_bf16(acc[0][1], al0, bh0[1], bh0[3]);
            mma_bf16(acc[0][2], al0, bh1[0], bh1[2]);
            mma_bf16(acc[0][3], al0, bh1[1], bh1[3]);
            mma_bf16(acc[1][0], al1, bh0[0], bh0[2]);
            mma_bf16(acc[1][1], al1, bh0[1], bh0[3]);
            mma_bf16(acc[1][2], al1, bh1[0], bh1[2]);
            mma_bf16(acc[1][3], al1, bh1[1], bh1[3]);
        }
        __syncthreads();
    }

    #pragma unroll
    for (int mf = 0; mf < 2; mf++) {
        #pragma unroll
        for (int e = 0; e < 2; e++) {
            int row = m0 + wm + mf * 16 + g + e * 8;
            #pragma unroll
            for (int nf = 0; nf < 4; nf++) {
                int col = j0 + wn + nf * 8 + 2 * j;
                float v0 = (acc[mf][nf][e * 2 + 0] + bias[col])     * oscale;
                float v1 = (acc[mf][nf][e * 2 + 1] + bias[col + 1]) * oscale;
                if (ROUND) {
                    v0 = __uint_as_float(f2tf32(v0));
                    v1 = __uint_as_float(f2tf32(v1));
                }
                float2 val = make_float2(v0, v1);
                if (HEAD_MAJOR) {
                    int bb = row >> 11, n = row & (N_ - 1);
                    int d  = col - j0;
                    *reinterpret_cast<float2*>(
                        &out[(((size_t)bb * H_ + blockIdx.x) * N_ + n) * 64 + d]) = val;
                } else {
                    *reinterpret_cast<float2*>(&out[(size_t)row * 1024 + col]) = val;
                }
            }
        }
    }
}

// --------------------- register-resident flash attention --------------------
// q-tile 128, 256 threads (8 warps, warp owns 16 q rows), key-tile 64.
// Each K/V tile now serves 128 q rows (2x data reuse, half the barriers/row).
// S accumulators are INITIALIZED with attn_bias (mma accumulates QK^T on top).
// smem floats: Ks[2][64][68] @0 | Vs[2][64][72] @8704 | Ps[8][16][68] @17920
// total 26624 floats = 106,496 B; 2 CTAs = 213 KB <= 228 KB carveout.
__global__ __launch_bounds__(256, 2)
void attn_kernel(const float* __restrict__ Qg, const float* __restrict__ Kg,
                 const float* __restrict__ Vg, const float* __restrict__ bias,
                 __nv_bfloat16* __restrict__ Ohi)
{
    extern __shared__ __align__(16) float sf[];
    const int tid  = threadIdx.x;
    const int lane = tid & 31, warp = tid >> 5;
    const int g    = lane >> 2, j = lane & 3;
    const int q0   = blockIdx.x * 128, h = blockIdx.y, b = blockIdx.z;
    const size_t bh = ((size_t)b * H_ + h) * N_;
    const int wq   = warp * 16;
    float* Psw = sf + 17920 + warp * 1088;
    const unsigned sbase = s_u32(sf);
    __nv_bfloat16* Olo = Ohi + (size_t)4096 * 1024;

    unsigned qa[8][4];
    {
        const float* q0p = Qg + (bh + q0 + wq + g) * 64;
        const float* q1p = q0p + 8 * 64;
        #pragma unroll
        for (int dk = 0; dk < 8; dk++) {
            qa[dk][0] = __float_as_uint(q0p[dk * 8 + j]);
            qa[dk][1] = __float_as_uint(q1p[dk * 8 + j]);
            qa[dk][2] = __float_as_uint(q0p[dk * 8 + j + 4]);
            qa[dk][3] = __float_as_uint(q1p[dk * 8 + j + 4]);
        }
    }

    float Oa[8][4];
    #pragma unroll
    for (int nb = 0; nb < 8; nb++)
        #pragma unroll
        for (int e = 0; e < 4; e++) Oa[nb][e] = 0.0f;
    float m0r = -1e30f, m1r = -1e30f, l0 = 0.0f, l1 = 0.0f;

    auto issue_kv = [&](int k0, int stg) {
        unsigned kbase = sbase + (unsigned)(stg * 4352) * 4u;
        unsigned vbase = sbase + (unsigned)(8704 + stg * 4608) * 4u;
        const float* Kp = Kg + (bh + k0) * 64;
        const float* Vp = Vg + (bh + k0) * 64;
        #pragma unroll
        for (int i = 0; i < 4; i++) {
            int c = tid + i * 256;
            int r = c >> 4, cc = (c & 15) * 4;
            cp16(kbase + (unsigned)(r * 68 + cc) * 4u, Kp + r * 64 + cc);
            cp16(vbase + (unsigned)(r * 72 + cc) * 4u, Vp + r * 64 + cc);
        }
    };

    issue_kv(0, 0);
    CP_COMMIT();

    const float* bb0 = bias + ((size_t)h * N_ + q0 + wq + g) * N_;
    const float* bb1 = bb0 + (size_t)8 * N_;

    for (int t = 0; t < 32; t++) {
        if (t + 1 < 32) { issue_kv((t + 1) * 64, (t + 1) & 1); CP_COMMIT(); CP_WAIT1(); }
        else            { CP_WAIT0(); }
        __syncthreads();

        const float* Ks = sf + (t & 1) * 4352;
        const float* Vs = sf + 8704 + (t & 1) * 4608;
        const int kcol = t * 64;

        // S accumulators initialized with bias; QK^T mmas accumulate on top.
        float sa[8][4];
        #pragma unroll
        for (int nb = 0; nb < 8; nb++) {
            float2 t0 = *reinterpret_cast<const float2*>(bb0 + kcol + nb * 8 + 2 * j);
            float2 t1 = *reinterpret_cast<const float2*>(bb1 + kcol + nb * 8 + 2 * j);
            sa[nb][0] = t0.x; sa[nb][1] = t0.y;
            sa[nb][2] = t1.x; sa[nb][3] = t1.y;
        }
        #pragma unroll
        for (int dk = 0; dk < 8; dk++)
            #pragma unroll
            for (int nb = 0; nb < 8; nb++) {
                const float* kp = Ks + (nb * 8 + g) * 68 + dk * 8 + j;
                mma_tf32(sa[nb], qa[dk], __float_as_uint(kp[0]),
                                         __float_as_uint(kp[4]));
            }

        float mx0 = -1e30f, mx1 = -1e30f;
        #pragma unroll
        for (int nb = 0; nb < 8; nb++) {
            mx0 = fmaxf(mx0, fmaxf(sa[nb][0], sa[nb][1]));
            mx1 = fmaxf(mx1, fmaxf(sa[nb][2], sa[nb][3]));
        }
        mx0 = fmaxf(mx0, __shfl_xor_sync(0xffffffffu, mx0, 1));
        mx0 = fmaxf(mx0, __shfl_xor_sync(0xffffffffu, mx0, 2));
        mx1 = fmaxf(mx1, __shfl_xor_sync(0xffffffffu, mx1, 1));
        mx1 = fmaxf(mx1, __shfl_xor_sync(0xffffffffu, mx1, 2));
        float mn0 = fmaxf(m0r, mx0), mn1 = fmaxf(m1r, mx1);
        float al0 = __expf(m0r - mn0), al1 = __expf(m1r - mn1);
        m0r = mn0; m1r = mn1;

        __syncwarp();
        float s0 = 0.0f, s1 = 0.0f;
        #pragma unroll
        for (int nb = 0; nb < 8; nb++) {
            float p0 = __expf(sa[nb][0] - mn0);
            float p1 = __expf(sa[nb][1] - mn0);
            float p2 = __expf(sa[nb][2] - mn1);
            float p3 = __expf(sa[nb][3] - mn1);
            s0 += p0 + p1; s1 += p2 + p3;
            Psw[g * 68 + nb * 8 + 2 * j]           = __uint_as_float(f2tf32(p0));
            Psw[g * 68 + nb * 8 + 2 * j + 1]       = __uint_as_float(f2tf32(p1));
            Psw[(g + 8) * 68 + nb * 8 + 2 * j]     = __uint_as_float(f2tf32(p2));
            Psw[(g + 8) * 68 + nb * 8 + 2 * j + 1] = __uint_as_float(f2tf32(p3));
            Oa[nb][0] *= al0; Oa[nb][1] *= al0;
            Oa[nb][2] *= al1; Oa[nb][3] *= al1;
        }
        s0 += __shfl_xor_sync(0xffffffffu, s0, 1);
        s0 += __shfl_xor_sync(0xffffffffu, s0, 2);
        s1 += __shfl_xor_sync(0xffffffffu, s1, 1);
        s1 += __shfl_xor_sync(0xffffffffu, s1, 2);
        l0 = l0 * al0 + s0;
        l1 = l1 * al1 + s1;
        __syncwarp();

        #pragma unroll
        for (int kk = 0; kk < 8; kk++) {
            unsigned pa[4];
            pa[0] = __float_as_uint(Psw[g * 68 + kk * 8 + j]);
            pa[1] = __float_as_uint(Psw[(g + 8) * 68 + kk * 8 + j]);
            pa[2] = __float_as_uint(Psw[g * 68 + kk * 8 + j + 4]);
            pa[3] = __float_as_uint(Psw[(g + 8) * 68 + kk * 8 + j + 4]);
            #pragma unroll
            for (int nb = 0; nb < 8; nb++) {
                const float* vp = Vs + (kk * 8 + j) * 72 + nb * 8 + g;
                mma_tf32(Oa[nb], pa, __float_as_uint(vp[0]),
                                     __float_as_uint(vp[4 * 72]));
            }
        }
        __syncthreads();
    }

    const float li0 = 1.0f / l0, li1 = 1.0f / l1;
    const size_t row0 = ((size_t)b * N_ + q0 + wq + g) * 1024;
    const size_t row1 = row0 + (size_t)8 * 1024;
    #pragma unroll
    for (int nb = 0; nb < 8; nb++) {
        const size_t c = (size_t)h * 64 + nb * 8 + 2 * j;
        float v0 = Oa[nb][0] * li0, v1 = Oa[nb][1] * li0;
        float v2 = Oa[nb][2] * li1, v3 = Oa[nb][3] * li1;
        __nv_bfloat16 h0 = __float2bfloat16_rn(v0);
        __nv_bfloat16 h1 = __float2bfloat16_rn(v1);
        __nv_bfloat16 h2 = __float2bfloat16_rn(v2);
        __nv_bfloat16 h3 = __float2bfloat16_rn(v3);
        __nv_bfloat16 e0 = __float2bfloat16_rn(v0 - __bfloat162float(h0));
        __nv_bfloat16 e1 = __float2bfloat16_rn(v1 - __bfloat162float(h1));
        __nv_bfloat16 e2 = __float2bfloat16_rn(v2 - __bfloat162float(h2));
        __nv_bfloat16 e3 = __float2bfloat16_rn(v3 - __bfloat162float(h3));
        *reinterpret_cast<__nv_bfloat162*>(Ohi + row0 + c) = __halves2bfloat162(h0, h1);
        *reinterpret_cast<__nv_bfloat162*>(Ohi + row1 + c) = __halves2bfloat162(h2, h3);
        *reinterpret_cast<__nv_bfloat162*>(Olo + row0 + c) = __halves2bfloat162(e0, e1);
        *reinterpret_cast<__nv_bfloat162*>(Olo + row1 + c) = __halves2bfloat162(e2, e3);
    }
}

// --------------------------------- launcher ---------------------------------
extern "C" void kernel_launch(void* const* d_in, const int* in_sizes, int n_in,
                              void* d_out, int out_size)
{
    (void)in_sizes; (void)n_in; (void)out_size;
    const float* x    = (const float*)d_in[0];
    const float* ctx  = (const float*)d_in[1];
    const float* bias = (const float*)d_in[2];
    const float* Wq   = (const float*)d_in[3];
    const float* bq   = (const float*)d_in[4];
    const float* Wk   = (const float*)d_in[5];
    const float* bk   = (const float*)d_in[6];
    const float* Wv   = (const float*)d_in[7];
    const float* bv   = (const float*)d_in[8];
    const float* Wo   = (const float*)d_in[9];
    const float* bo   = (const float*)d_in[10];
    float* out = (float*)d_out;

    float *qp, *kp, *vp;
    __nv_bfloat16 *xs, *cs, *os, *ws;
    cudaGetSymbolAddress((void**)&qp, g_Q);
    cudaGetSymbolAddress((void**)&kp, g_K);
    cudaGetSymbolAddress((void**)&vp, g_V);
    cudaGetSymbolAddress((void**)&xs, g_Xs);
    cudaGetSymbolAddress((void**)&cs, g_Cs);
    cudaGetSymbolAddress((void**)&os, g_Os);
    cudaGetSymbolAddress((void**)&ws, g_Ws);

    const int proj_smem = 7680 * 2 * 4;   // 61,440 B (x3 CTAs = 184 KB)
    const int attn_smem = 26624 * 4;      // 106,496 B (x2 CTAs = 213 KB)
    cudaFuncSetAttribute(proj_bf16_kernel<true , true >,
        cudaFuncAttributeMaxDynamicSharedMemorySize, proj_smem);
    cudaFuncSetAttribute(proj_bf16_kernel<false, false>,
        cudaFuncAttributeMaxDynamicSharedMemorySize, proj_smem);
    cudaFuncSetAttribute(attn_kernel,
        cudaFuncAttributeMaxDynamicSharedMemorySize, attn_smem);
    cudaFuncSetAttribute(proj_bf16_kernel<true , true >,
        cudaFuncAttributePreferredSharedMemoryCarveout, 100);
    cudaFuncSetAttribute(proj_bf16_kernel<false, false>,
        cudaFuncAttributePreferredSharedMemoryCarveout, 100);
    cudaFuncSetAttribute(attn_kernel,
        cudaFuncAttributePreferredSharedMemoryCarveout, 100);

    const size_t WPITCH = (size_t)2 * 1024 * 1024;  // hi+lo plane per weight

    // 1) all splits in one launch
    split_all_kernel<<<12288, 256>>>(x, ctx, Wq, Wk, Wv, Wo, xs, cs, ws);

    // 2) merged Q/K/V projections (gridDim.z = 3)
    ProjArgs pa;
    pa.A[0] = xs; pa.Wp[0] = ws + 0 * WPITCH; pa.bias[0] = bq; pa.out[0] = qp; pa.scale[0] = 0.125f;
    pa.A[1] = cs; pa.Wp[1] = ws + 1 * WPITCH; pa.bias[1] = bk; pa.out[1] = kp; pa.scale[1] = 1.0f;
    pa.A[2] = cs; pa.Wp[2] = ws + 2 * WPITCH; pa.bias[2] = bv; pa.out[2] = vp; pa.scale[2] = 1.0f;
    dim3 gp(16, 32, 3);   // (C/64, 4096/128, QKV)
    proj_bf16_kernel<true , true ><<<gp, 256, proj_smem>>>(pa);

    // 3) attention (q-tile 128, writes bf16 split planes directly)
    dim3 ga(N_ / 128, H_, B_);   // (16, 16, 2)
    attn_kernel<<<ga, 256, attn_smem>>>(qp, kp, vp, bias, os);

    // 4) output projection
    ProjArgs po;
    po.A[0] = os; po.Wp[0] = ws + 3 * WPITCH; po.bias[0] = bo; po.out[0] = out; po.scale[0] = 1.0f;
    po.A[1] = po.A[0]; po.Wp[1] = po.Wp[0]; po.bias[1] = po.bias[0]; po.out[1] = po.out[0]; po.scale[1] = 1.0f;
    po.A[2] = po.A[0]; po.Wp[2] = po.Wp[0]; po.bias[2] = po.bias[0]; po.out[2] = po.out[0]; po.scale[2] = 1.0f;
    dim3 go(16, 32, 1);
    proj_bf16_kernel<false, false><<<go, 256, proj_smem>>>(po);
}

// round 15
// speedup vs baseline: 1.3531x; 1.3527x over previous
#include <cuda_runtime.h>
#include <cuda_fp16.h>
#include <cstdint>

#define B_ 2
#define N_ 2048
#define C_ 1024
#define H_ 16
#define D_ 64

// ------------------------- scratch (__device__ globals) ----------------------
__device__ float g_Q[(size_t)B_*H_*N_*D_];   // tf32-rounded, pre-scaled by 1/8
__device__ float g_K[(size_t)B_*H_*N_*D_];   // tf32-rounded
__device__ float g_V[(size_t)B_*H_*N_*D_];   // tf32-rounded

__device__ __half g_Xh[(size_t)4096*1024];       // x   -> fp16 (single plane)
__device__ __half g_Ch[(size_t)4096*1024];       // ctx -> fp16
__device__ __half g_Oh[(size_t)2*4096*1024];     // attn out: fp16 hi plane, lo plane
__device__ __half g_Wh[(size_t)4*1024*1024];     // 4 weights, fp16 single plane

// ------------------------------- PTX helpers --------------------------------
__device__ __forceinline__ unsigned f2tf32(float f) {
    unsigned o; asm("cvt.rna.tf32.f32 %0, %1;" : "=r"(o) : "f"(f)); return o;
}
__device__ __forceinline__ void mma_tf32(float c[4], const unsigned a[4],
                                         unsigned b0, unsigned b1) {
    asm volatile("mma.sync.aligned.m16n8k8.row.col.f32.tf32.tf32.f32 "
        "{%0,%1,%2,%3}, {%4,%5,%6,%7}, {%8,%9}, {%0,%1,%2,%3};"
        : "+f"(c[0]), "+f"(c[1]), "+f"(c[2]), "+f"(c[3])
        : "r"(a[0]), "r"(a[1]), "r"(a[2]), "r"(a[3]), "r"(b0), "r"(b1));
}
__device__ __forceinline__ void mma_f16(float c[4], const unsigned a[4],
                                        unsigned b0, unsigned b1) {
    asm volatile("mma.sync.aligned.m16n8k16.row.col.f32.f16.f16.f32 "
        "{%0,%1,%2,%3}, {%4,%5,%6,%7}, {%8,%9}, {%0,%1,%2,%3};"
        : "+f"(c[0]), "+f"(c[1]), "+f"(c[2]), "+f"(c[3])
        : "r"(a[0]), "r"(a[1]), "r"(a[2]), "r"(a[3]), "r"(b0), "r"(b1));
}
__device__ __forceinline__ void ldmx4(unsigned addr, unsigned r[4]) {
    asm volatile("ldmatrix.sync.aligned.m8n8.x4.shared.b16 {%0,%1,%2,%3}, [%4];"
        : "=r"(r[0]), "=r"(r[1]), "=r"(r[2]), "=r"(r[3]) : "r"(addr));
}
__device__ __forceinline__ void cp16(unsigned dst, const void* src) {
    asm volatile("cp.async.cg.shared.global [%0], [%1], 16;" :: "r"(dst), "l"(src));
}
#define CP_COMMIT() asm volatile("cp.async.commit_group;")
#define CP_WAIT1()  asm volatile("cp.async.wait_group 1;")
#define CP_WAIT0()  asm volatile("cp.async.wait_group 0;")
__device__ __forceinline__ unsigned s_u32(const void* p) {
    return (unsigned)__cvta_generic_to_shared(p);
}

// ----------------------- fp32 -> fp16 convert kernel -------------------------
// Grid: [0,4096) x | [4096,8192) ctx | [8192,12288) weights (1024 blocks each).
__global__ __launch_bounds__(256)
void conv_all_kernel(const float* __restrict__ x, const float* __restrict__ ctx,
                     const float* __restrict__ Wq, const float* __restrict__ Wk,
                     const float* __restrict__ Wv, const float* __restrict__ Wo,
                     __half* __restrict__ xh, __half* __restrict__ ch,
                     __half* __restrict__ wh)
{
    int blk = blockIdx.x;
    const float* src;
    __half* dst;
    int n4;
    if (blk < 4096)      { src = x;   dst = xh; n4 = 1048576; }
    else if (blk < 8192) { src = ctx; dst = ch; n4 = 1048576; blk -= 4096; }
    else {
        int w = (blk - 8192) >> 10;
        blk = (blk - 8192) & 1023;
        n4 = 262144;
        src = (w == 0) ? Wq : (w == 1) ? Wk : (w == 2) ? Wv : Wo;
        dst = wh + (size_t)w * 1048576u;
    }
    int i = blk * 256 + threadIdx.x;
    if (i >= n4) return;
    float4 v = reinterpret_cast<const float4*>(src)[i];
    __half2* d2 = reinterpret_cast<__half2*>(dst);
    d2[2*i+0] = __floats2half2_rn(v.x, v.y);
    d2[2*i+1] = __floats2half2_rn(v.z, v.w);
}

// -------------------------- fp16 GEMM (projections) --------------------------
// out[4096, 1024] = A @ W^T + bias. A has APLANES fp16 planes (1 = single
// precision-fp16 path for QKV; 2 = hi/lo split path for the O projection,
// error then comes only from the single-fp16 W). W is single fp16.
// Block 256 thr (8 warps: 4m x 2n), tile 128x64, BK=64, cp.async 2 stages.
// smem rows are 64 fp16 = 128B, padded stride 144B (conflict-free ldmatrix:
// 8-row address sets step by 16B mod 128). Addressing fully hoisted.
struct ProjArgs {
    const __half* A[3];
    const __half* Wp[3];
    const float* bias[3];
    float* out[3];
    float scale[3];
};

template<int APLANES, bool HEAD_MAJOR, bool ROUND>
__global__ __launch_bounds__(256, (APLANES == 1) ? 3 : 2)
void proj_fp16_kernel(ProjArgs args)
{
    constexpr int A_BYTES     = APLANES * 128 * 144;      // 18432 or 36864
    constexpr int STAGE_BYTES = A_BYTES + 64 * 144;       // +9216

    extern __shared__ __align__(16) char smem[];
    const int z = blockIdx.z;
    const __half* A    = args.A[z];
    const __half* W    = args.Wp[z];
    const float* bias  = args.bias[z];
    float* out         = args.out[z];
    const float oscale = args.scale[z];

    const int tid  = threadIdx.x;
    const int lane = tid & 31, warp = tid >> 5;
    const int wm   = (warp >> 1) * 32, wn = (warp & 1) * 32;
    const int g    = lane >> 2, j = lane & 3;
    const int m0   = blockIdx.y * 128, j0 = blockIdx.x * 64;
    const unsigned sbase = s_u32(smem);

    float acc[2][4][4];
    #pragma unroll
    for (int a = 0; a < 2; a++)
        #pragma unroll
        for (int b = 0; b < 4; b++)
            #pragma unroll
            for (int c = 0; c < 4; c++) acc[a][b][c] = 0.0f;

    // --- hoisted loader addressing (per-thread, computed once) ---
    const char* asrc[4 * APLANES];
    unsigned    adst[4 * APLANES];
    #pragma unroll
    for (int i = 0; i < 4 * APLANES; i++) {
        int c   = tid + i * 256;             // 0 .. 1024*APLANES-1
        int pl  = c >> 10, cc = c & 1023;
        int row = cc >> 3, q = cc & 7;
        const __half* ap = A + (size_t)pl * (4096u * 1024u);
        asrc[i] = (const char*)(ap + (size_t)(m0 + row) * 1024 + q * 8);
        adst[i] = sbase + (unsigned)(pl * 18432 + row * 144 + q * 16);
    }
    const char* bsrc[2];
    unsigned    bdst[2];
    #pragma unroll
    for (int i = 0; i < 2; i++) {
        int c   = tid + i * 256;             // 0..511
        int row = c >> 3, q = c & 7;
        bsrc[i] = (const char*)(W + (size_t)(j0 + row) * 1024 + q * 8);
        bdst[i] = sbase + (unsigned)(A_BYTES + row * 144 + q * 16);
    }

    auto issue_tile = [&](unsigned ktB, unsigned so) {
        #pragma unroll
        for (int i = 0; i < 4 * APLANES; i++) cp16(adst[i] + so, asrc[i] + ktB);
        #pragma unroll
        for (int i = 0; i < 2; i++)           cp16(bdst[i] + so, bsrc[i] + ktB);
    };

    issue_tile(0u, 0u);
    CP_COMMIT();

    // ldmatrix per-thread offsets (bytes, relative to stage base)
    const unsigned lrow = (unsigned)(lane & 15);
    const unsigned lkb  = (unsigned)(lane >> 4) * 16u;
    const unsigned aoff = (wm + lrow) * 144u + lkb;
    const unsigned boff = (unsigned)A_BYTES + (wn + lrow) * 144u + lkb;

    for (int t = 0; t < 16; t++) {
        if (t < 15) {
            issue_tile((unsigned)(t + 1) * 128u,
                       ((t + 1) & 1) ? (unsigned)STAGE_BYTES : 0u);
            CP_COMMIT(); CP_WAIT1();
        } else {
            CP_WAIT0();
        }
        __syncthreads();

        const unsigned sb = sbase + ((t & 1) ? (unsigned)STAGE_BYTES : 0u);
        #pragma unroll
        for (int ks = 0; ks < 4; ks++) {
            const unsigned ko = (unsigned)ks * 32u;
            unsigned a0[4], a1[4], b0[4], b1[4];
            ldmx4(sb + aoff + ko,         a0);   // A hi rows wm..wm+15
            ldmx4(sb + aoff + 2304u + ko, a1);   // A hi rows wm+16..31
            ldmx4(sb + boff + ko,         b0);   // B n wn..+15 (nf0: r0/r2, nf1: r1/r3)
            ldmx4(sb + boff + 2304u + ko, b1);   // B n wn+16..+31 (nf2, nf3)

            mma_f16(acc[0][0], a0, b0[0], b0[2]);
            mma_f16(acc[0][1], a0, b0[1], b0[3]);
            mma_f16(acc[0][2], a0, b1[0], b1[2]);
            mma_f16(acc[0][3], a0, b1[1], b1[3]);
            mma_f16(acc[1][0], a1, b0[0], b0[2]);
            mma_f16(acc[1][1], a1, b0[1], b0[3]);
            mma_f16(acc[1][2], a1, b1[0], b1[2]);
            mma_f16(acc[1][3], a1, b1[1], b1[3]);

            if (APLANES == 2) {
                unsigned c0[4], c1[4];
                ldmx4(sb + aoff + 18432u + ko,         c0);  // A lo rows wm..+15
                ldmx4(sb + aoff + 18432u + 2304u + ko, c1);  // A lo rows wm+16..31
                mma_f16(acc[0][0], c0, b0[0], b0[2]);
                mma_f16(acc[0][1], c0, b0[1], b0[3]);
                mma_f16(acc[0][2], c0, b1[0], b1[2]);
                mma_f16(acc[0][3], c0, b1[1], b1[3]);
                mma_f16(acc[1][0], c1, b0[0], b0[2]);
                mma_f16(acc[1][1], c1, b0[1], b0[3]);
                mma_f16(acc[1][2], c1, b1[0], b1[2]);
                mma_f16(acc[1][3], c1, b1[1], b1[3]);
            }
        }
        __syncthreads();
    }

    #pragma unroll
    for (int mf = 0; mf < 2; mf++) {
        #pragma unroll
        for (int e = 0; e < 2; e++) {
            int row = m0 + wm + mf * 16 + g + e * 8;
            #pragma unroll
            for (int nf = 0; nf < 4; nf++) {
                int col = j0 + wn + nf * 8 + 2 * j;
                float v0 = (acc[mf][nf][e * 2 + 0] + bias[col])     * oscale;
                float v1 = (acc[mf][nf][e * 2 + 1] + bias[col + 1]) * oscale;
                if (ROUND) {
                    v0 = __uint_as_float(f2tf32(v0));
                    v1 = __uint_as_float(f2tf32(v1));
                }
                float2 val = make_float2(v0, v1);
                if (HEAD_MAJOR) {
                    int bb = row >> 11, n = row & (N_ - 1);
                    int d  = col - j0;
                    *reinterpret_cast<float2*>(
                        &out[(((size_t)bb * H_ + blockIdx.x) * N_ + n) * 64 + d]) = val;
                } else {
                    *reinterpret_cast<float2*>(&out[(size_t)row * 1024 + col]) = val;
                }
            }
        }
    }
}

// --------------------- register-resident flash attention --------------------
// Identical numerics to round 14 (passed, rel_err 2.997e-4). Epilogue now
// writes the output as fp16 hi/lo planes (feeds the 2-term O projection).
__global__ __launch_bounds__(256, 2)
void attn_kernel(const float* __restrict__ Qg, const float* __restrict__ Kg,
                 const float* __restrict__ Vg, const float* __restrict__ bias,
                 __half* __restrict__ Ohi)
{
    extern __shared__ __align__(16) float sf[];
    const int tid  = threadIdx.x;
    const int lane = tid & 31, warp = tid >> 5;
    const int g    = lane >> 2, j = lane & 3;
    const int q0   = blockIdx.x * 128, h = blockIdx.y, b = blockIdx.z;
    const size_t bh = ((size_t)b * H_ + h) * N_;
    const int wq   = warp * 16;
    float* Psw = sf + 17920 + warp * 1088;
    const unsigned sbase = s_u32(sf);
    __half* Olo = Ohi + (size_t)4096 * 1024;

    unsigned qa[8][4];
    {
        const float* q0p = Qg + (bh + q0 + wq + g) * 64;
        const float* q1p = q0p + 8 * 64;
        #pragma unroll
        for (int dk = 0; dk < 8; dk++) {
            qa[dk][0] = __float_as_uint(q0p[dk * 8 + j]);
            qa[dk][1] = __float_as_uint(q1p[dk * 8 + j]);
            qa[dk][2] = __float_as_uint(q0p[dk * 8 + j + 4]);
            qa[dk][3] = __float_as_uint(q1p[dk * 8 + j + 4]);
        }
    }

    float Oa[8][4];
    #pragma unroll
    for (int nb = 0; nb < 8; nb++)
        #pragma unroll
        for (int e = 0; e < 4; e++) Oa[nb][e] = 0.0f;
    float m0r = -1e30f, m1r = -1e30f, l0 = 0.0f, l1 = 0.0f;

    auto issue_kv = [&](int k0, int stg) {
        unsigned kbase = sbase + (unsigned)(stg * 4352) * 4u;
        unsigned vbase = sbase + (unsigned)(8704 + stg * 4608) * 4u;
        const float* Kp = Kg + (bh + k0) * 64;
        const float* Vp = Vg + (bh + k0) * 64;
        #pragma unroll
        for (int i = 0; i < 4; i++) {
            int c = tid + i * 256;
            int r = c >> 4, cc = (c & 15) * 4;
            cp16(kbase + (unsigned)(r * 68 + cc) * 4u, Kp + r * 64 + cc);
            cp16(vbase + (unsigned)(r * 72 + cc) * 4u, Vp + r * 64 + cc);
        }
    };

    issue_kv(0, 0);
    CP_COMMIT();

    const float* bb0 = bias + ((size_t)h * N_ + q0 + wq + g) * N_;
    const float* bb1 = bb0 + (size_t)8 * N_;

    for (int t = 0; t < 32; t++) {
        if (t + 1 < 32) { issue_kv((t + 1) * 64, (t + 1) & 1); CP_COMMIT(); CP_WAIT1(); }
        else            { CP_WAIT0(); }
        __syncthreads();

        const float* Ks = sf + (t & 1) * 4352;
        const float* Vs = sf + 8704 + (t & 1) * 4608;
        const int kcol = t * 64;

        float sa[8][4];
        #pragma unroll
        for (int nb = 0; nb < 8; nb++) {
            float2 t0 = *reinterpret_cast<const float2*>(bb0 + kcol + nb * 8 + 2 * j);
            float2 t1 = *reinterpret_cast<const float2*>(bb1 + kcol + nb * 8 + 2 * j);
            sa[nb][0] = t0.x; sa[nb][1] = t0.y;
            sa[nb][2] = t1.x; sa[nb][3] = t1.y;
        }
        #pragma unroll
        for (int dk = 0; dk < 8; dk++)
            #pragma unroll
            for (int nb = 0; nb < 8; nb++) {
                const float* kp = Ks + (nb * 8 + g) * 68 + dk * 8 + j;
                mma_tf32(sa[nb], qa[dk], __float_as_uint(kp[0]),
                                         __float_as_uint(kp[4]));
            }

        float mx0 = -1e30f, mx1 = -1e30f;
        #pragma unroll
        for (int nb = 0; nb < 8; nb++) {
            mx0 = fmaxf(mx0, fmaxf(sa[nb][0], sa[nb][1]));
            mx1 = fmaxf(mx1, fmaxf(sa[nb][2], sa[nb][3]));
        }
        mx0 = fmaxf(mx0, __shfl_xor_sync(0xffffffffu, mx0, 1));
        mx0 = fmaxf(mx0, __shfl_xor_sync(0xffffffffu, mx0, 2));
        mx1 = fmaxf(mx1, __shfl_xor_sync(0xffffffffu, mx1, 1));
        mx1 = fmaxf(mx1, __shfl_xor_sync(0xffffffffu, mx1, 2));
        float mn0 = fmaxf(m0r, mx0), mn1 = fmaxf(m1r, mx1);
        float al0 = __expf(m0r - mn0), al1 = __expf(m1r - mn1);
        m0r = mn0; m1r = mn1;

        __syncwarp();
        float s0 = 0.0f, s1 = 0.0f;
        #pragma unroll
        for (int nb = 0; nb < 8; nb++) {
            float p0 = __expf(sa[nb][0] - mn0);
            float p1 = __expf(sa[nb][1] - mn0);
            float p2 = __expf(sa[nb][2] - mn1);
            float p3 = __expf(sa[nb][3] - mn1);
            s0 += p0 + p1; s1 += p2 + p3;
            Psw[g * 68 + nb * 8 + 2 * j]           = __uint_as_float(f2tf32(p0));
            Psw[g * 68 + nb * 8 + 2 * j + 1]       = __uint_as_float(f2tf32(p1));
            Psw[(g + 8) * 68 + nb * 8 + 2 * j]     = __uint_as_float(f2tf32(p2));
            Psw[(g + 8) * 68 + nb * 8 + 2 * j + 1] = __uint_as_float(f2tf32(p3));
            Oa[nb][0] *= al0; Oa[nb][1] *= al0;
            Oa[nb][2] *= al1; Oa[nb][3] *= al1;
        }
        s0 += __shfl_xor_sync(0xffffffffu, s0, 1);
        s0 += __shfl_xor_sync(0xffffffffu, s0, 2);
        s1 += __shfl_xor_sync(0xffffffffu, s1, 1);
        s1 += __shfl_xor_sync(0xffffffffu, s1, 2);
        l0 = l0 * al0 + s0;
        l1 = l1 * al1 + s1;
        __syncwarp();

        #pragma unroll
        for (int kk = 0; kk < 8; kk++) {
            unsigned pa[4];
            pa[0] = __float_as_uint(Psw[g * 68 + kk * 8 + j]);
            pa[1] = __float_as_uint(Psw[(g + 8) * 68 + kk * 8 + j]);
            pa[2] = __float_as_uint(Psw[g * 68 + kk * 8 + j + 4]);
            pa[3] = __float_as_uint(Psw[(g + 8) * 68 + kk * 8 + j + 4]);
            #pragma unroll
            for (int nb = 0; nb < 8; nb++) {
                const float* vp = Vs + (kk * 8 + j) * 72 + nb * 8 + g;
                mma_tf32(Oa[nb], pa, __float_as_uint(vp[0]),
                                     __float_as_uint(vp[4 * 72]));
            }
        }
        __syncthreads();
    }

    // Epilogue: normalize, write fp16 hi/lo planes (for the 2-term O proj).
    const float li0 = 1.0f / l0, li1 = 1.0f / l1;
    const size_t row0 = ((size_t)b * N_ + q0 + wq + g) * 1024;
    const size_t row1 = row0 + (size_t)8 * 1024;
    #pragma unroll
    for (int nb = 0; nb < 8; nb++) {
        const size_t c = (size_t)h * 64 + nb * 8 + 2 * j;
        float v0 = Oa[nb][0] * li0, v1 = Oa[nb][1] * li0;
        float v2 = Oa[nb][2] * li1, v3 = Oa[nb][3] * li1;
        __half h0 = __float2half_rn(v0);
        __half h1 = __float2half_rn(v1);
        __half h2 = __float2half_rn(v2);
        __half h3 = __float2half_rn(v3);
        __half e0 = __float2half_rn(v0 - __half2float(h0));
        __half e1 = __float2half_rn(v1 - __half2float(h1));
        __half e2 = __float2half_rn(v2 - __half2float(h2));
        __half e3 = __float2half_rn(v3 - __half2float(h3));
        *reinterpret_cast<__half2*>(Ohi + row0 + c) = __halves2half2(h0, h1);
        *reinterpret_cast<__half2*>(Ohi + row1 + c) = __halves2half2(h2, h3);
        *reinterpret_cast<__half2*>(Olo + row0 + c) = __halves2half2(e0, e1);
        *reinterpret_cast<__half2*>(Olo + row1 + c) = __halves2half2(e2, e3);
    }
}

// --------------------------------- launcher ---------------------------------
extern "C" void kernel_launch(void* const* d_in, const int* in_sizes, int n_in,
                              void* d_out, int out_size)
{
    (void)in_sizes; (void)n_in; (void)out_size;
    const float* x    = (const float*)d_in[0];
    const float* ctx  = (const float*)d_in[1];
    const float* bias = (const float*)d_in[2];
    const float* Wq   = (const float*)d_in[3];
    const float* bq   = (const float*)d_in[4];
    const float* Wk   = (const float*)d_in[5];
    const float* bk   = (const float*)d_in[6];
    const float* Wv   = (const float*)d_in[7];
    const float* bv   = (const float*)d_in[8];
    const float* Wo   = (const float*)d_in[9];
    const float* bo   = (const float*)d_in[10];
    float* out = (float*)d_out;

    float *qp, *kp, *vp;
    __half *xh, *ch, *oh, *wh;
    cudaGetSymbolAddress((void**)&qp, g_Q);
    cudaGetSymbolAddress((void**)&kp, g_K);
    cudaGetSymbolAddress((void**)&vp, g_V);
    cudaGetSymbolAddress((void**)&xh, g_Xh);
    cudaGetSymbolAddress((void**)&ch, g_Ch);
    cudaGetSymbolAddress((void**)&oh, g_Oh);
    cudaGetSymbolAddress((void**)&wh, g_Wh);

    const int qkv_smem  = 2 * 27648;     // 55,296 B  (3 CTAs = 166 KB)
    const int oprj_smem = 2 * 46080;     // 92,160 B  (2 CTAs = 184 KB)
    const int attn_smem = 26624 * 4;     // 106,496 B (2 CTAs = 213 KB)
    cudaFuncSetAttribute(proj_fp16_kernel<1, true , true >,
        cudaFuncAttributeMaxDynamicSharedMemorySize, qkv_smem);
    cudaFuncSetAttribute(proj_fp16_kernel<2, false, false>,
        cudaFuncAttributeMaxDynamicSharedMemorySize, oprj_smem);
    cudaFuncSetAttribute(attn_kernel,
        cudaFuncAttributeMaxDynamicSharedMemorySize, attn_smem);
    cudaFuncSetAttribute(proj_fp16_kernel<1, true , true >,
        cudaFuncAttributePreferredSharedMemoryCarveout, 100);
    cudaFuncSetAttribute(proj_fp16_kernel<2, false, false>,
        cudaFuncAttributePreferredSharedMemoryCarveout, 100);
    cudaFuncSetAttribute(attn_kernel,
        cudaFuncAttributePreferredSharedMemoryCarveout, 100);

    // 1) fp32 -> fp16 conversions (one launch)
    conv_all_kernel<<<12288, 256>>>(x, ctx, Wq, Wk, Wv, Wo, xh, ch, wh);

    // 2) merged Q/K/V projections, single-fp16 (gridDim.z = 3)
    ProjArgs pa;
    pa.A[0] = xh; pa.Wp[0] = wh + 0u * 1048576u; pa.bias[0] = bq; pa.out[0] = qp; pa.scale[0] = 0.125f;
    pa.A[1] = ch; pa.Wp[1] = wh + 1u * 1048576u; pa.bias[1] = bk; pa.out[1] = kp; pa.scale[1] = 1.0f;
    pa.A[2] = ch; pa.Wp[2] = wh + 2u * 1048576u; pa.bias[2] = bv; pa.out[2] = vp; pa.scale[2] = 1.0f;
    dim3 gp(16, 32, 3);
    proj_fp16_kernel<1, true , true ><<<gp, 256, qkv_smem>>>(pa);

    // 3) attention (q-tile 128, writes fp16 hi/lo planes)
    dim3 ga(N_ / 128, H_, B_);   // (16, 16, 2)
    attn_kernel<<<ga, 256, attn_smem>>>(qp, kp, vp, bias, oh);

    // 4) output projection: 2-term (attn-out hi/lo fp16) x single-fp16 Wo
    ProjArgs po;
    po.A[0] = oh; po.Wp[0] = wh + 3u * 1048576u; po.bias[0] = bo; po.out[0] = out; po.scale[0] = 1.0f;
    po.A[1] = po.A[0]; po.Wp[1] = po.Wp[0]; po.bias[1] = po.bias[0]; po.out[1] = po.out[0]; po.scale[1] = 1.0f;
    po.A[2] = po.A[0]; po.Wp[2] = po.Wp[0]; po.bias[2] = po.bias[0]; po.out[2] = po.out[0]; po.scale[2] = 1.0f;
    dim3 go(16, 32, 1);
    proj_fp16_kernel<2, false, false><<<go, 256, oprj_smem>>>(po);
}

// round 16
// speedup vs baseline: 1.8498x; 1.3671x over previous
#include <cuda_runtime.h>
#include <cuda_fp16.h>
#include <cstdint>

#define B_ 2
#define N_ 2048
#define C_ 1024
#define H_ 16
#define D_ 64

// ------------------------- scratch (__device__ globals) ----------------------
__device__ __half g_Qh[(size_t)B_*H_*N_*D_];     // fp16, pre-scaled by 1/8
__device__ __half g_Kh[(size_t)B_*H_*N_*D_];     // fp16
__device__ __half g_Vh[(size_t)B_*H_*N_*D_];     // fp16
__device__ __half g_Xh[(size_t)4096*1024];       // x   -> fp16
__device__ __half g_Ch[(size_t)4096*1024];       // ctx -> fp16
__device__ __half g_Oh[(size_t)2*4096*1024];     // attn out: fp16 hi, lo planes
__device__ __half g_Wh[(size_t)4*1024*1024];     // 4 weights, fp16

// ------------------------------- PTX helpers --------------------------------
__device__ __forceinline__ void mma_f16(float c[4], const unsigned a[4],
                                        unsigned b0, unsigned b1) {
    asm volatile("mma.sync.aligned.m16n8k16.row.col.f32.f16.f16.f32 "
        "{%0,%1,%2,%3}, {%4,%5,%6,%7}, {%8,%9}, {%0,%1,%2,%3};"
        : "+f"(c[0]), "+f"(c[1]), "+f"(c[2]), "+f"(c[3])
        : "r"(a[0]), "r"(a[1]), "r"(a[2]), "r"(a[3]), "r"(b0), "r"(b1));
}
__device__ __forceinline__ void ldmx4(unsigned addr, unsigned r[4]) {
    asm volatile("ldmatrix.sync.aligned.m8n8.x4.shared.b16 {%0,%1,%2,%3}, [%4];"
        : "=r"(r[0]), "=r"(r[1]), "=r"(r[2]), "=r"(r[3]) : "r"(addr));
}
__device__ __forceinline__ void ldmx4t(unsigned addr, unsigned r[4]) {
    asm volatile("ldmatrix.sync.aligned.m8n8.x4.trans.shared.b16 {%0,%1,%2,%3}, [%4];"
        : "=r"(r[0]), "=r"(r[1]), "=r"(r[2]), "=r"(r[3]) : "r"(addr));
}
__device__ __forceinline__ unsigned packh2(float a, float b) {
    __half2 h = __floats2half2_rn(a, b);
    return *reinterpret_cast<unsigned*>(&h);
}
__device__ __forceinline__ void cp16(unsigned dst, const void* src) {
    asm volatile("cp.async.cg.shared.global [%0], [%1], 16;" :: "r"(dst), "l"(src));
}
#define CP_COMMIT() asm volatile("cp.async.commit_group;")
#define CP_WAIT1()  asm volatile("cp.async.wait_group 1;")
#define CP_WAIT0()  asm volatile("cp.async.wait_group 0;")
__device__ __forceinline__ unsigned s_u32(const void* p) {
    return (unsigned)__cvta_generic_to_shared(p);
}

// ----------------------- fp32 -> fp16 convert kernel -------------------------
__global__ __launch_bounds__(256)
void conv_all_kernel(const float* __restrict__ x, const float* __restrict__ ctx,
                     const float* __restrict__ Wq, const float* __restrict__ Wk,
                     const float* __restrict__ Wv, const float* __restrict__ Wo,
                     __half* __restrict__ xh, __half* __restrict__ ch,
                     __half* __restrict__ wh)
{
    int blk = blockIdx.x;
    const float* src;
    __half* dst;
    int n4;
    if (blk < 4096)      { src = x;   dst = xh; n4 = 1048576; }
    else if (blk < 8192) { src = ctx; dst = ch; n4 = 1048576; blk -= 4096; }
    else {
        int w = (blk - 8192) >> 10;
        blk = (blk - 8192) & 1023;
        n4 = 262144;
        src = (w == 0) ? Wq : (w == 1) ? Wk : (w == 2) ? Wv : Wo;
        dst = wh + (size_t)w * 1048576u;
    }
    int i = blk * 256 + threadIdx.x;
    if (i >= n4) return;
    float4 v = reinterpret_cast<const float4*>(src)[i];
    __half2* d2 = reinterpret_cast<__half2*>(dst);
    d2[2*i+0] = __floats2half2_rn(v.x, v.y);
    d2[2*i+1] = __floats2half2_rn(v.z, v.w);
}

// -------------------------- fp16 GEMM (projections) --------------------------
// OMODE 1: write fp16 head-major (QKV). OMODE 0: write fp32 row-major (O).
struct ProjArgs {
    const __half* A[3];
    const __half* Wp[3];
    const float* bias[3];
    void* out[3];
    float scale[3];
};

template<int APLANES, int OMODE>
__global__ __launch_bounds__(256, (APLANES == 1) ? 3 : 2)
void proj_fp16_kernel(ProjArgs args)
{
    constexpr int A_BYTES     = APLANES * 128 * 144;
    constexpr int STAGE_BYTES = A_BYTES + 64 * 144;

    extern __shared__ __align__(16) char smem[];
    const int z = blockIdx.z;
    const __half* A    = args.A[z];
    const __half* W    = args.Wp[z];
    const float* bias  = args.bias[z];
    void* out          = args.out[z];
    const float oscale = args.scale[z];

    const int tid  = threadIdx.x;
    const int lane = tid & 31, warp = tid >> 5;
    const int wm   = (warp >> 1) * 32, wn = (warp & 1) * 32;
    const int g    = lane >> 2, j = lane & 3;
    const int m0   = blockIdx.y * 128, j0 = blockIdx.x * 64;
    const unsigned sbase = s_u32(smem);

    float acc[2][4][4];
    #pragma unroll
    for (int a = 0; a < 2; a++)
        #pragma unroll
        for (int b = 0; b < 4; b++)
            #pragma unroll
            for (int c = 0; c < 4; c++) acc[a][b][c] = 0.0f;

    const char* asrc[4 * APLANES];
    unsigned    adst[4 * APLANES];
    #pragma unroll
    for (int i = 0; i < 4 * APLANES; i++) {
        int c   = tid + i * 256;
        int pl  = c >> 10, cc = c & 1023;
        int row = cc >> 3, q = cc & 7;
        const __half* ap = A + (size_t)pl * (4096u * 1024u);
        asrc[i] = (const char*)(ap + (size_t)(m0 + row) * 1024 + q * 8);
        adst[i] = sbase + (unsigned)(pl * 18432 + row * 144 + q * 16);
    }
    const char* bsrc[2];
    unsigned    bdst[2];
    #pragma unroll
    for (int i = 0; i < 2; i++) {
        int c   = tid + i * 256;
        int row = c >> 3, q = c & 7;
        bsrc[i] = (const char*)(W + (size_t)(j0 + row) * 1024 + q * 8);
        bdst[i] = sbase + (unsigned)(A_BYTES + row * 144 + q * 16);
    }

    auto issue_tile = [&](unsigned ktB, unsigned so) {
        #pragma unroll
        for (int i = 0; i < 4 * APLANES; i++) cp16(adst[i] + so, asrc[i] + ktB);
        #pragma unroll
        for (int i = 0; i < 2; i++)           cp16(bdst[i] + so, bsrc[i] + ktB);
    };

    issue_tile(0u, 0u);
    CP_COMMIT();

    const unsigned lrow = (unsigned)(lane & 15);
    const unsigned lkb  = (unsigned)(lane >> 4) * 16u;
    const unsigned aoff = (wm + lrow) * 144u + lkb;
    const unsigned boff = (unsigned)A_BYTES + (wn + lrow) * 144u + lkb;

    for (int t = 0; t < 16; t++) {
        if (t < 15) {
            issue_tile((unsigned)(t + 1) * 128u,
                       ((t + 1) & 1) ? (unsigned)STAGE_BYTES : 0u);
            CP_COMMIT(); CP_WAIT1();
        } else {
            CP_WAIT0();
        }
        __syncthreads();

        const unsigned sb = sbase + ((t & 1) ? (unsigned)STAGE_BYTES : 0u);
        #pragma unroll
        for (int ks = 0; ks < 4; ks++) {
            const unsigned ko = (unsigned)ks * 32u;
            unsigned a0[4], a1[4], b0[4], b1[4];
            ldmx4(sb + aoff + ko,         a0);
            ldmx4(sb + aoff + 2304u + ko, a1);
            ldmx4(sb + boff + ko,         b0);
            ldmx4(sb + boff + 2304u + ko, b1);

            mma_f16(acc[0][0], a0, b0[0], b0[2]);
            mma_f16(acc[0][1], a0, b0[1], b0[3]);
            mma_f16(acc[0][2], a0, b1[0], b1[2]);
            mma_f16(acc[0][3], a0, b1[1], b1[3]);
            mma_f16(acc[1][0], a1, b0[0], b0[2]);
            mma_f16(acc[1][1], a1, b0[1], b0[3]);
            mma_f16(acc[1][2], a1, b1[0], b1[2]);
            mma_f16(acc[1][3], a1, b1[1], b1[3]);

            if (APLANES == 2) {
                unsigned c0[4], c1[4];
                ldmx4(sb + aoff + 18432u + ko,         c0);
                ldmx4(sb + aoff + 18432u + 2304u + ko, c1);
                mma_f16(acc[0][0], c0, b0[0], b0[2]);
                mma_f16(acc[0][1], c0, b0[1], b0[3]);
                mma_f16(acc[0][2], c0, b1[0], b1[2]);
                mma_f16(acc[0][3], c0, b1[1], b1[3]);
                mma_f16(acc[1][0], c1, b0[0], b0[2]);
                mma_f16(acc[1][1], c1, b0[1], b0[3]);
                mma_f16(acc[1][2], c1, b1[0], b1[2]);
                mma_f16(acc[1][3], c1, b1[1], b1[3]);
            }
        }
        __syncthreads();
    }

    #pragma unroll
    for (int mf = 0; mf < 2; mf++) {
        #pragma unroll
        for (int e = 0; e < 2; e++) {
            int row = m0 + wm + mf * 16 + g + e * 8;
            #pragma unroll
            for (int nf = 0; nf < 4; nf++) {
                int col = j0 + wn + nf * 8 + 2 * j;
                float v0 = (acc[mf][nf][e * 2 + 0] + bias[col])     * oscale;
                float v1 = (acc[mf][nf][e * 2 + 1] + bias[col + 1]) * oscale;
                if (OMODE == 1) {
                    int bb = row >> 11, n = row & (N_ - 1);
                    int head = col >> 6, d = col & 63;
                    *reinterpret_cast<__half2*>((__half*)out +
                        ((((size_t)bb * H_ + head) * N_ + n) * 64 + d)) =
                        __floats2half2_rn(v0, v1);
                } else {
                    *reinterpret_cast<float2*>((float*)out + (size_t)row * 1024 + col) =
                        make_float2(v0, v1);
                }
            }
        }
    }
}

// --------------------- fp16 register-resident flash attention ----------------
// q-tile 128 (8 warps x 16 rows), key-tile 128 (two 64-key compute halves).
// fp16 m16n8k16 for QK^T and PV (same 10-bit mantissa as the old tf32 path).
// P stays in registers (S-accum layout == fp16 A-fragment layout).
// smem: Ks[2][128][144B] @0 | Vs[2][128][144B] @36864 = 73,728 B (2 CTAs/SM).
__global__ __launch_bounds__(256, 2)
void attn_kernel(const __half* __restrict__ Qg, const __half* __restrict__ Kg,
                 const __half* __restrict__ Vg, const float* __restrict__ bias,
                 __half* __restrict__ Ohi)
{
    extern __shared__ __align__(16) char smem[];
    const int tid  = threadIdx.x;
    const int lane = tid & 31, warp = tid >> 5;
    const int g    = lane >> 2, j = lane & 3;
    const int q0   = blockIdx.x * 128, h = blockIdx.y, b = blockIdx.z;
    const size_t bh = ((size_t)b * H_ + h) * N_;
    const int wq   = warp * 16;
    const unsigned sbase = s_u32(smem);
    __half* Olo = Ohi + (size_t)4096 * 1024;

    // Q fragments straight from gmem (fp16, pre-scaled)
    unsigned qa[4][4];
    {
        const __half* qb0 = Qg + (bh + q0 + wq + g) * 64;
        const __half* qb1 = qb0 + 8 * 64;
        #pragma unroll
        for (int ks = 0; ks < 4; ks++) {
            qa[ks][0] = *reinterpret_cast<const unsigned*>(qb0 + ks * 16 + 2 * j);
            qa[ks][1] = *reinterpret_cast<const unsigned*>(qb1 + ks * 16 + 2 * j);
            qa[ks][2] = *reinterpret_cast<const unsigned*>(qb0 + ks * 16 + 8 + 2 * j);
            qa[ks][3] = *reinterpret_cast<const unsigned*>(qb1 + ks * 16 + 8 + 2 * j);
        }
    }

    float Oa[8][4];
    #pragma unroll
    for (int nb = 0; nb < 8; nb++)
        #pragma unroll
        for (int e = 0; e < 4; e++) Oa[nb][e] = 0.0f;
    float m0r = -1e30f, m1r = -1e30f, l0 = 0.0f, l1 = 0.0f;

    auto issue_kv = [&](int k0, int stg) {
        unsigned kb = sbase + (unsigned)stg * 18432u;
        unsigned vb = sbase + 36864u + (unsigned)stg * 18432u;
        const __half* Kp = Kg + (bh + k0) * 64;
        const __half* Vp = Vg + (bh + k0) * 64;
        #pragma unroll
        for (int i = 0; i < 4; i++) {
            int c = tid + i * 256;           // 0..1023
            int r = c >> 3, q8 = c & 7;
            cp16(kb + (unsigned)(r * 144 + q8 * 16), Kp + r * 64 + q8 * 8);
            cp16(vb + (unsigned)(r * 144 + q8 * 16), Vp + r * 64 + q8 * 8);
        }
    };

    issue_kv(0, 0);
    CP_COMMIT();

    const float* bb0 = bias + ((size_t)h * N_ + q0 + wq + g) * N_;
    const float* bb1 = bb0 + (size_t)8 * N_;
    const unsigned lr = (unsigned)(lane & 15) * 144u;
    const unsigned lc = (unsigned)(lane >> 4) * 16u;

    for (int t = 0; t < 16; t++) {
        if (t + 1 < 16) { issue_kv((t + 1) * 128, (t + 1) & 1); CP_COMMIT(); CP_WAIT1(); }
        else            { CP_WAIT0(); }
        __syncthreads();

        const unsigned kst = sbase + (unsigned)(t & 1) * 18432u;
        const unsigned vst = kst + 36864u;

        #pragma unroll
        for (int hs = 0; hs < 2; hs++) {
            const int kcol = t * 128 + hs * 64;
            const unsigned hoff = (unsigned)hs * 64u * 144u;

            // S accumulators initialized with bias; QK^T accumulates on top.
            float sa[8][4];
            #pragma unroll
            for (int nb = 0; nb < 8; nb++) {
                float2 t0 = *reinterpret_cast<const float2*>(bb0 + kcol + nb * 8 + 2 * j);
                float2 t1 = *reinterpret_cast<const float2*>(bb1 + kcol + nb * 8 + 2 * j);
                sa[nb][0] = t0.x; sa[nb][1] = t0.y;
                sa[nb][2] = t1.x; sa[nb][3] = t1.y;
            }
            #pragma unroll
            for (int ks = 0; ks < 4; ks++) {
                #pragma unroll
                for (int np = 0; np < 4; np++) {
                    unsigned kb[4];
                    ldmx4(kst + hoff + (unsigned)np * (16u * 144u) + lr +
                          (unsigned)ks * 32u + lc, kb);
                    mma_f16(sa[2*np],   qa[ks], kb[0], kb[2]);
                    mma_f16(sa[2*np+1], qa[ks], kb[1], kb[3]);
                }
            }

            // online softmax (register stats); P packed to fp16 in registers.
            float mx0 = -1e30f, mx1 = -1e30f;
            #pragma unroll
            for (int nb = 0; nb < 8; nb++) {
                mx0 = fmaxf(mx0, fmaxf(sa[nb][0], sa[nb][1]));
                mx1 = fmaxf(mx1, fmaxf(sa[nb][2], sa[nb][3]));
            }
            mx0 = fmaxf(mx0, __shfl_xor_sync(0xffffffffu, mx0, 1));
            mx0 = fmaxf(mx0, __shfl_xor_sync(0xffffffffu, mx0, 2));
            mx1 = fmaxf(mx1, __shfl_xor_sync(0xffffffffu, mx1, 1));
            mx1 = fmaxf(mx1, __shfl_xor_sync(0xffffffffu, mx1, 2));
            float mn0 = fmaxf(m0r, mx0), mn1 = fmaxf(m1r, mx1);
            float al0 = __expf(m0r - mn0), al1 = __expf(m1r - mn1);
            m0r = mn0; m1r = mn1;

            unsigned ph[8][2];
            float s0 = 0.0f, s1 = 0.0f;
            #pragma unroll
            for (int nb = 0; nb < 8; nb++) {
                float p0 = __expf(sa[nb][0] - mn0);
                float p1 = __expf(sa[nb][1] - mn0);
                float p2 = __expf(sa[nb][2] - mn1);
                float p3 = __expf(sa[nb][3] - mn1);
                s0 += p0 + p1; s1 += p2 + p3;
                ph[nb][0] = packh2(p0, p1);
                ph[nb][1] = packh2(p2, p3);
                Oa[nb][0] *= al0; Oa[nb][1] *= al0;
                Oa[nb][2] *= al1; Oa[nb][3] *= al1;
            }
            s0 += __shfl_xor_sync(0xffffffffu, s0, 1);
            s0 += __shfl_xor_sync(0xffffffffu, s0, 2);
            s1 += __shfl_xor_sync(0xffffffffu, s1, 1);
            s1 += __shfl_xor_sync(0xffffffffu, s1, 2);
            l0 = l0 * al0 + s0;
            l1 = l1 * al1 + s1;

            // O += P @ V   (V fragments via ldmatrix.trans from k-major smem)
            #pragma unroll
            for (int kk = 0; kk < 4; kk++) {
                unsigned pa[4] = { ph[2*kk][0], ph[2*kk][1],
                                   ph[2*kk+1][0], ph[2*kk+1][1] };
                #pragma unroll
                for (int dp = 0; dp < 4; dp++) {
                    unsigned vb[4];
                    ldmx4t(vst + hoff + (unsigned)kk * (16u * 144u) + lr +
                           (unsigned)dp * 32u + lc, vb);
                    mma_f16(Oa[2*dp],   pa, vb[0], vb[1]);
                    mma_f16(Oa[2*dp+1], pa, vb[2], vb[3]);
                }
            }
        }
        __syncthreads();
    }

    // Epilogue: normalize, write fp16 hi/lo planes for the 2-term O proj.
    const float li0 = 1.0f / l0, li1 = 1.0f / l1;
    const size_t row0 = ((size_t)b * N_ + q0 + wq + g) * 1024;
    const size_t row1 = row0 + (size_t)8 * 1024;
    #pragma unroll
    for (int nb = 0; nb < 8; nb++) {
        const size_t c = (size_t)h * 64 + nb * 8 + 2 * j;
        float v0 = Oa[nb][0] * li0, v1 = Oa[nb][1] * li0;
        float v2 = Oa[nb][2] * li1, v3 = Oa[nb][3] * li1;
        __half h0 = __float2half_rn(v0);
        __half h1 = __float2half_rn(v1);
        __half h2 = __float2half_rn(v2);
        __half h3 = __float2half_rn(v3);
        __half e0 = __float2half_rn(v0 - __half2float(h0));
        __half e1 = __float2half_rn(v1 - __half2float(h1));
        __half e2 = __float2half_rn(v2 - __half2float(h2));
        __half e3 = __float2half_rn(v3 - __half2float(h3));
        *reinterpret_cast<__half2*>(Ohi + row0 + c) = __halves2half2(h0, h1);
        *reinterpret_cast<__half2*>(Ohi + row1 + c) = __halves2half2(h2, h3);
        *reinterpret_cast<__half2*>(Olo + row0 + c) = __halves2half2(e0, e1);
        *reinterpret_cast<__half2*>(Olo + row1 + c) = __halves2half2(e2, e3);
    }
}

// --------------------------------- launcher ---------------------------------
extern "C" void kernel_launch(void* const* d_in, const int* in_sizes, int n_in,
                              void* d_out, int out_size)
{
    (void)in_sizes; (void)n_in; (void)out_size;
    const float* x    = (const float*)d_in[0];
    const float* ctx  = (const float*)d_in[1];
    const float* bias = (const float*)d_in[2];
    const float* Wq   = (const float*)d_in[3];
    const float* bq   = (const float*)d_in[4];
    const float* Wk   = (const float*)d_in[5];
    const float* bk   = (const float*)d_in[6];
    const float* Wv   = (const float*)d_in[7];
    const float* bv   = (const float*)d_in[8];
    const float* Wo   = (const float*)d_in[9];
    const float* bo   = (const float*)d_in[10];
    float* out = (float*)d_out;

    __half *qh, *kh, *vh, *xh, *ch, *oh, *wh;
    cudaGetSymbolAddress((void**)&qh, g_Qh);
    cudaGetSymbolAddress((void**)&kh, g_Kh);
    cudaGetSymbolAddress((void**)&vh, g_Vh);
    cudaGetSymbolAddress((void**)&xh, g_Xh);
    cudaGetSymbolAddress((void**)&ch, g_Ch);
    cudaGetSymbolAddress((void**)&oh, g_Oh);
    cudaGetSymbolAddress((void**)&wh, g_Wh);

    const int qkv_smem  = 2 * 27648;     // 55,296 B (3 CTAs)
    const int oprj_smem = 2 * 46080;     // 92,160 B (2 CTAs)
    const int attn_smem = 73728;         // 73,728 B (2 CTAs)
    cudaFuncSetAttribute(proj_fp16_kernel<1, 1>,
        cudaFuncAttributeMaxDynamicSharedMemorySize, qkv_smem);
    cudaFuncSetAttribute(proj_fp16_kernel<2, 0>,
        cudaFuncAttributeMaxDynamicSharedMemorySize, oprj_smem);
    cudaFuncSetAttribute(attn_kernel,
        cudaFuncAttributeMaxDynamicSharedMemorySize, attn_smem);
    cudaFuncSetAttribute(proj_fp16_kernel<1, 1>,
        cudaFuncAttributePreferredSharedMemoryCarveout, 100);
    cudaFuncSetAttribute(proj_fp16_kernel<2, 0>,
        cudaFuncAttributePreferredSharedMemoryCarveout, 100);
    cudaFuncSetAttribute(attn_kernel,
        cudaFuncAttributePreferredSharedMemoryCarveout, 100);

    // 1) fp32 -> fp16 conversions
    conv_all_kernel<<<12288, 256>>>(x, ctx, Wq, Wk, Wv, Wo, xh, ch, wh);

    // 2) merged Q/K/V projections, single-fp16, fp16 head-major output
    ProjArgs pa;
    pa.A[0] = xh; pa.Wp[0] = wh + 0u * 1048576u; pa.bias[0] = bq; pa.out[0] = qh; pa.scale[0] = 0.125f;
    pa.A[1] = ch; pa.Wp[1] = wh + 1u * 1048576u; pa.bias[1] = bk; pa.out[1] = kh; pa.scale[1] = 1.0f;
    pa.A[2] = ch; pa.Wp[2] = wh + 2u * 1048576u; pa.bias[2] = bv; pa.out[2] = vh; pa.scale[2] = 1.0f;
    dim3 gp(16, 32, 3);
    proj_fp16_kernel<1, 1><<<gp, 256, qkv_smem>>>(pa);

    // 3) attention (fp16 mma, q-tile 128, key-tile 128)
    dim3 ga(N_ / 128, H_, B_);   // (16, 16, 2)
    attn_kernel<<<ga, 256, attn_smem>>>(qh, kh, vh, bias, oh);

    // 4) output projection: 2-term fp16 split x single-fp16 Wo
    ProjArgs po;
    po.A[0] = oh; po.Wp[0] = wh + 3u * 1048576u; po.bias[0] = bo; po.out[0] = out; po.scale[0] = 1.0f;
    po.A[1] = po.A[0]; po.Wp[1] = po.Wp[0]; po.bias[1] = po.bias[0]; po.out[1] = po.out[0]; po.scale[1] = 1.0f;
    po.A[2] = po.A[0]; po.Wp[2] = po.Wp[0]; po.bias[2] = po.bias[0]; po.out[2] = po.out[0]; po.scale[2] = 1.0f;
    dim3 go(16, 32, 1);
    proj_fp16_kernel<2, 0><<<go, 256, oprj_smem>>>(po);
}

// round 17
// speedup vs baseline: 1.9972x; 1.0797x over previous
#include <cuda_runtime.h>
#include <cuda_fp16.h>
#include <cstdint>

#define B_ 2
#define N_ 2048
#define C_ 1024
#define H_ 16
#define D_ 64

// ------------------------- scratch (__device__ globals) ----------------------
__device__ __half g_Qh[(size_t)B_*H_*N_*D_];     // fp16, pre-scaled by 1/8
__device__ __half g_Kh[(size_t)B_*H_*N_*D_];     // fp16
__device__ __half g_Vh[(size_t)B_*H_*N_*D_];     // fp16
__device__ __half g_Xh[(size_t)4096*1024];       // x   -> fp16
__device__ __half g_Ch[(size_t)4096*1024];       // ctx -> fp16
__device__ __half g_Oh[(size_t)4096*1024];       // attn out, fp16 (single plane)
__device__ __half g_Wh[(size_t)4*1024*1024];     // 4 weights, fp16

// ------------------------------- PTX helpers --------------------------------
__device__ __forceinline__ void mma_f16(float c[4], const unsigned a[4],
                                        unsigned b0, unsigned b1) {
    asm volatile("mma.sync.aligned.m16n8k16.row.col.f32.f16.f16.f32 "
        "{%0,%1,%2,%3}, {%4,%5,%6,%7}, {%8,%9}, {%0,%1,%2,%3};"
        : "+f"(c[0]), "+f"(c[1]), "+f"(c[2]), "+f"(c[3])
        : "r"(a[0]), "r"(a[1]), "r"(a[2]), "r"(a[3]), "r"(b0), "r"(b1));
}
__device__ __forceinline__ void ldmx4(unsigned addr, unsigned r[4]) {
    asm volatile("ldmatrix.sync.aligned.m8n8.x4.shared.b16 {%0,%1,%2,%3}, [%4];"
        : "=r"(r[0]), "=r"(r[1]), "=r"(r[2]), "=r"(r[3]) : "r"(addr));
}
__device__ __forceinline__ void ldmx4t(unsigned addr, unsigned r[4]) {
    asm volatile("ldmatrix.sync.aligned.m8n8.x4.trans.shared.b16 {%0,%1,%2,%3}, [%4];"
        : "=r"(r[0]), "=r"(r[1]), "=r"(r[2]), "=r"(r[3]) : "r"(addr));
}
__device__ __forceinline__ unsigned packh2(float a, float b) {
    __half2 h = __floats2half2_rn(a, b);
    return *reinterpret_cast<unsigned*>(&h);
}
__device__ __forceinline__ void cp16(unsigned dst, const void* src) {
    asm volatile("cp.async.cg.shared.global [%0], [%1], 16;" :: "r"(dst), "l"(src));
}
#define CP_COMMIT() asm volatile("cp.async.commit_group;")
#define CP_WAIT1()  asm volatile("cp.async.wait_group 1;")
#define CP_WAIT0()  asm volatile("cp.async.wait_group 0;")
__device__ __forceinline__ unsigned s_u32(const void* p) {
    return (unsigned)__cvta_generic_to_shared(p);
}

// ----------------------- fp32 -> fp16 convert kernel -------------------------
__global__ __launch_bounds__(256)
void conv_all_kernel(const float* __restrict__ x, const float* __restrict__ ctx,
                     const float* __restrict__ Wq, const float* __restrict__ Wk,
                     const float* __restrict__ Wv, const float* __restrict__ Wo,
                     __half* __restrict__ xh, __half* __restrict__ ch,
                     __half* __restrict__ wh)
{
    int blk = blockIdx.x;
    const float* src;
    __half* dst;
    int n4;
    if (blk < 4096)      { src = x;   dst = xh; n4 = 1048576; }
    else if (blk < 8192) { src = ctx; dst = ch; n4 = 1048576; blk -= 4096; }
    else {
        int w = (blk - 8192) >> 10;
        blk = (blk - 8192) & 1023;
        n4 = 262144;
        src = (w == 0) ? Wq : (w == 1) ? Wk : (w == 2) ? Wv : Wo;
        dst = wh + (size_t)w * 1048576u;
    }
    int i = blk * 256 + threadIdx.x;
    if (i >= n4) return;
    float4 v = reinterpret_cast<const float4*>(src)[i];
    __half2* d2 = reinterpret_cast<__half2*>(dst);
    d2[2*i+0] = __floats2half2_rn(v.x, v.y);
    d2[2*i+1] = __floats2half2_rn(v.z, v.w);
}

// ----------------------- fp16 GEMM (all 4 projections) -----------------------
// out[4096,1024] = A @ W^T + bias, single-fp16 operands.
// Block 256 thr (8 warps: 4m x 2n), tile 128x64, BK=64, cp.async 2 stages,
// 4 CTAs/SM (smem 4x55,296 = 221 KB; regs capped at 64 via hoisted
// single-base + immediate-offset addressing: chunk i differs by constant
// +65536 B in gmem / +4608 B in smem since row = (tid>>3) + 32*i).
// OMODE 1: fp16 head-major out (QKV). OMODE 0: fp32 row-major out (O).
struct ProjArgs {
    const __half* A[3];
    const __half* Wp[3];
    const float* bias[3];
    void* out[3];
    float scale[3];
};

template<int OMODE>
__global__ __launch_bounds__(256, 4)
void proj_fp16_kernel(ProjArgs args)
{
    constexpr unsigned A_BYTES     = 128u * 144u;          // 18432
    constexpr unsigned STAGE_BYTES = A_BYTES + 64u * 144u; // 27648

    extern __shared__ __align__(16) char smem[];
    const int z = blockIdx.z;
    const __half* A    = args.A[z];
    const __half* W    = args.Wp[z];
    const float* bias  = args.bias[z];
    void* out          = args.out[z];
    const float oscale = args.scale[z];

    const int tid  = threadIdx.x;
    const int lane = tid & 31, warp = tid >> 5;
    const int wm   = (warp >> 1) * 32, wn = (warp & 1) * 32;
    const int g    = lane >> 2, j = lane & 3;
    const int m0   = blockIdx.y * 128, j0 = blockIdx.x * 64;
    const unsigned sbase = s_u32(smem);

    float acc[2][4][4];
    #pragma unroll
    for (int a = 0; a < 2; a++)
        #pragma unroll
        for (int b = 0; b < 4; b++)
            #pragma unroll
            for (int c = 0; c < 4; c++) acc[a][b][c] = 0.0f;

    // single-base hoisted loader addressing
    const int trow = tid >> 3, tq = tid & 7;
    const char* asrc0 = (const char*)(A + (size_t)(m0 + trow) * 1024 + tq * 8);
    const char* bsrc0 = (const char*)(W + (size_t)(j0 + trow) * 1024 + tq * 8);
    const unsigned adst0 = sbase + (unsigned)(trow * 144 + tq * 16);
    const unsigned bdst0 = adst0 + A_BYTES;

    auto issue_tile = [&](unsigned ktB, unsigned so) {
        #pragma unroll
        for (unsigned i = 0; i < 4; i++)
            cp16(adst0 + so + i * 4608u, asrc0 + ktB + i * 65536u);
        #pragma unroll
        for (unsigned i = 0; i < 2; i++)
            cp16(bdst0 + so + i * 4608u, bsrc0 + ktB + i * 65536u);
    };

    issue_tile(0u, 0u);
    CP_COMMIT();

    const unsigned lrow = (unsigned)(lane & 15);
    const unsigned lkb  = (unsigned)(lane >> 4) * 16u;
    const unsigned aoff = (wm + lrow) * 144u + lkb;
    const unsigned boff = A_BYTES + (wn + lrow) * 144u + lkb;

    for (int t = 0; t < 16; t++) {
        if (t < 15) {
            issue_tile((unsigned)(t + 1) * 128u,
                       ((t + 1) & 1) ? STAGE_BYTES : 0u);
            CP_COMMIT(); CP_WAIT1();
        } else {
            CP_WAIT0();
        }
        __syncthreads();

        const unsigned sb = sbase + ((t & 1) ? STAGE_BYTES : 0u);
        #pragma unroll
        for (int ks = 0; ks < 4; ks++) {
            const unsigned ko = (unsigned)ks * 32u;
            unsigned a0[4], a1[4], b0[4], b1[4];
            ldmx4(sb + aoff + ko,         a0);
            ldmx4(sb + aoff + 2304u + ko, a1);
            ldmx4(sb + boff + ko,         b0);
            ldmx4(sb + boff + 2304u + ko, b1);

            mma_f16(acc[0][0], a0, b0[0], b0[2]);
            mma_f16(acc[0][1], a0, b0[1], b0[3]);
            mma_f16(acc[0][2], a0, b1[0], b1[2]);
            mma_f16(acc[0][3], a0, b1[1], b1[3]);
            mma_f16(acc[1][0], a1, b0[0], b0[2]);
            mma_f16(acc[1][1], a1, b0[1], b0[3]);
            mma_f16(acc[1][2], a1, b1[0], b1[2]);
            mma_f16(acc[1][3], a1, b1[1], b1[3]);
        }
        __syncthreads();
    }

    #pragma unroll
    for (int mf = 0; mf < 2; mf++) {
        #pragma unroll
        for (int e = 0; e < 2; e++) {
            int row = m0 + wm + mf * 16 + g + e * 8;
            #pragma unroll
            for (int nf = 0; nf < 4; nf++) {
                int col = j0 + wn + nf * 8 + 2 * j;
                float v0 = (acc[mf][nf][e * 2 + 0] + bias[col])     * oscale;
                float v1 = (acc[mf][nf][e * 2 + 1] + bias[col + 1]) * oscale;
                if (OMODE == 1) {
                    int bb = row >> 11, n = row & (N_ - 1);
                    int head = col >> 6, d = col & 63;
                    *reinterpret_cast<__half2*>((__half*)out +
                        ((((size_t)bb * H_ + head) * N_ + n) * 64 + d)) =
                        __floats2half2_rn(v0, v1);
                } else {
                    *reinterpret_cast<float2*>((float*)out + (size_t)row * 1024 + col) =
                        make_float2(v0, v1);
                }
            }
        }
    }
}

// --------------------- fp16 register-resident flash attention ----------------
// Unchanged numerics from round 16 (passed, 5.04e-4). Epilogue writes only the
// fp16 hi plane (feeds the 1-term O projection).
__global__ __launch_bounds__(256, 2)
void attn_kernel(const __half* __restrict__ Qg, const __half* __restrict__ Kg,
                 const __half* __restrict__ Vg, const float* __restrict__ bias,
                 __half* __restrict__ Og)
{
    extern __shared__ __align__(16) char smem[];
    const int tid  = threadIdx.x;
    const int lane = tid & 31, warp = tid >> 5;
    const int g    = lane >> 2, j = lane & 3;
    const int q0   = blockIdx.x * 128, h = blockIdx.y, b = blockIdx.z;
    const size_t bh = ((size_t)b * H_ + h) * N_;
    const int wq   = warp * 16;
    const unsigned sbase = s_u32(smem);

    unsigned qa[4][4];
    {
        const __half* qb0 = Qg + (bh + q0 + wq + g) * 64;
        const __half* qb1 = qb0 + 8 * 64;
        #pragma unroll
        for (int ks = 0; ks < 4; ks++) {
            qa[ks][0] = *reinterpret_cast<const unsigned*>(qb0 + ks * 16 + 2 * j);
            qa[ks][1] = *reinterpret_cast<const unsigned*>(qb1 + ks * 16 + 2 * j);
            qa[ks][2] = *reinterpret_cast<const unsigned*>(qb0 + ks * 16 + 8 + 2 * j);
            qa[ks][3] = *reinterpret_cast<const unsigned*>(qb1 + ks * 16 + 8 + 2 * j);
        }
    }

    float Oa[8][4];
    #pragma unroll
    for (int nb = 0; nb < 8; nb++)
        #pragma unroll
        for (int e = 0; e < 4; e++) Oa[nb][e] = 0.0f;
    float m0r = -1e30f, m1r = -1e30f, l0 = 0.0f, l1 = 0.0f;

    auto issue_kv = [&](int k0, int stg) {
        unsigned kb = sbase + (unsigned)stg * 18432u;
        unsigned vb = sbase + 36864u + (unsigned)stg * 18432u;
        const __half* Kp = Kg + (bh + k0) * 64;
        const __half* Vp = Vg + (bh + k0) * 64;
        #pragma unroll
        for (int i = 0; i < 4; i++) {
            int c = tid + i * 256;
            int r = c >> 3, q8 = c & 7;
            cp16(kb + (unsigned)(r * 144 + q8 * 16), Kp + r * 64 + q8 * 8);
            cp16(vb + (unsigned)(r * 144 + q8 * 16), Vp + r * 64 + q8 * 8);
        }
    };

    issue_kv(0, 0);
    CP_COMMIT();

    const float* bb0 = bias + ((size_t)h * N_ + q0 + wq + g) * N_;
    const float* bb1 = bb0 + (size_t)8 * N_;
    const unsigned lr = (unsigned)(lane & 15) * 144u;
    const unsigned lc = (unsigned)(lane >> 4) * 16u;

    for (int t = 0; t < 16; t++) {
        if (t + 1 < 16) { issue_kv((t + 1) * 128, (t + 1) & 1); CP_COMMIT(); CP_WAIT1(); }
        else            { CP_WAIT0(); }
        __syncthreads();

        const unsigned kst = sbase + (unsigned)(t & 1) * 18432u;
        const unsigned vst = kst + 36864u;

        #pragma unroll
        for (int hs = 0; hs < 2; hs++) {
            const int kcol = t * 128 + hs * 64;
            const unsigned hoff = (unsigned)hs * 64u * 144u;

            float sa[8][4];
            #pragma unroll
            for (int nb = 0; nb < 8; nb++) {
                float2 t0 = *reinterpret_cast<const float2*>(bb0 + kcol + nb * 8 + 2 * j);
                float2 t1 = *reinterpret_cast<const float2*>(bb1 + kcol + nb * 8 + 2 * j);
                sa[nb][0] = t0.x; sa[nb][1] = t0.y;
                sa[nb][2] = t1.x; sa[nb][3] = t1.y;
            }
            #pragma unroll
            for (int ks = 0; ks < 4; ks++) {
                #pragma unroll
                for (int np = 0; np < 4; np++) {
                    unsigned kb[4];
                    ldmx4(kst + hoff + (unsigned)np * (16u * 144u) + lr +
                          (unsigned)ks * 32u + lc, kb);
                    mma_f16(sa[2*np],   qa[ks], kb[0], kb[2]);
                    mma_f16(sa[2*np+1], qa[ks], kb[1], kb[3]);
                }
            }

            float mx0 = -1e30f, mx1 = -1e30f;
            #pragma unroll
            for (int nb = 0; nb < 8; nb++) {
                mx0 = fmaxf(mx0, fmaxf(sa[nb][0], sa[nb][1]));
                mx1 = fmaxf(mx1, fmaxf(sa[nb][2], sa[nb][3]));
            }
            mx0 = fmaxf(mx0, __shfl_xor_sync(0xffffffffu, mx0, 1));
            mx0 = fmaxf(mx0, __shfl_xor_sync(0xffffffffu, mx0, 2));
            mx1 = fmaxf(mx1, __shfl_xor_sync(0xffffffffu, mx1, 1));
            mx1 = fmaxf(mx1, __shfl_xor_sync(0xffffffffu, mx1, 2));
            float mn0 = fmaxf(m0r, mx0), mn1 = fmaxf(m1r, mx1);
            float al0 = __expf(m0r - mn0), al1 = __expf(m1r - mn1);
            m0r = mn0; m1r = mn1;

            unsigned ph[8][2];
            float s0 = 0.0f, s1 = 0.0f;
            #pragma unroll
            for (int nb = 0; nb < 8; nb++) {
                float p0 = __expf(sa[nb][0] - mn0);
                float p1 = __expf(sa[nb][1] - mn0);
                float p2 = __expf(sa[nb][2] - mn1);
                float p3 = __expf(sa[nb][3] - mn1);
                s0 += p0 + p1; s1 += p2 + p3;
                ph[nb][0] = packh2(p0, p1);
                ph[nb][1] = packh2(p2, p3);
                Oa[nb][0] *= al0; Oa[nb][1] *= al0;
                Oa[nb][2] *= al1; Oa[nb][3] *= al1;
            }
            s0 += __shfl_xor_sync(0xffffffffu, s0, 1);
            s0 += __shfl_xor_sync(0xffffffffu, s0, 2);
            s1 += __shfl_xor_sync(0xffffffffu, s1, 1);
            s1 += __shfl_xor_sync(0xffffffffu, s1, 2);
            l0 = l0 * al0 + s0;
            l1 = l1 * al1 + s1;

            #pragma unroll
            for (int kk = 0; kk < 4; kk++) {
                unsigned pa[4] = { ph[2*kk][0], ph[2*kk][1],
                                   ph[2*kk+1][0], ph[2*kk+1][1] };
                #pragma unroll
                for (int dp = 0; dp < 4; dp++) {
                    unsigned vb[4];
                    ldmx4t(vst + hoff + (unsigned)kk * (16u * 144u) + lr +
                           (unsigned)dp * 32u + lc, vb);
                    mma_f16(Oa[2*dp],   pa, vb[0], vb[1]);
                    mma_f16(Oa[2*dp+1], pa, vb[2], vb[3]);
                }
            }
        }
        __syncthreads();
    }

    // Epilogue: normalize, write fp16 (single plane) for the 1-term O proj.
    const float li0 = 1.0f / l0, li1 = 1.0f / l1;
    const size_t row0 = ((size_t)b * N_ + q0 + wq + g) * 1024;
    const size_t row1 = row0 + (size_t)8 * 1024;
    #pragma unroll
    for (int nb = 0; nb < 8; nb++) {
        const size_t c = (size_t)h * 64 + nb * 8 + 2 * j;
        *reinterpret_cast<__half2*>(Og + row0 + c) =
            __floats2half2_rn(Oa[nb][0] * li0, Oa[nb][1] * li0);
        *reinterpret_cast<__half2*>(Og + row1 + c) =
            __floats2half2_rn(Oa[nb][2] * li1, Oa[nb][3] * li1);
    }
}

// --------------------------------- launcher ---------------------------------
extern "C" void kernel_launch(void* const* d_in, const int* in_sizes, int n_in,
                              void* d_out, int out_size)
{
    (void)in_sizes; (void)n_in; (void)out_size;
    const float* x    = (const float*)d_in[0];
    const float* ctx  = (const float*)d_in[1];
    const float* bias = (const float*)d_in[2];
    const float* Wq   = (const float*)d_in[3];
    const float* bq   = (const float*)d_in[4];
    const float* Wk   = (const float*)d_in[5];
    const float* bk   = (const float*)d_in[6];
    const float* Wv   = (const float*)d_in[7];
    const float* bv   = (const float*)d_in[8];
    const float* Wo   = (const float*)d_in[9];
    const float* bo   = (const float*)d_in[10];
    float* out = (float*)d_out;

    __half *qh, *kh, *vh, *xh, *ch, *oh, *wh;
    cudaGetSymbolAddress((void**)&qh, g_Qh);
    cudaGetSymbolAddress((void**)&kh, g_Kh);
    cudaGetSymbolAddress((void**)&vh, g_Vh);
    cudaGetSymbolAddress((void**)&xh, g_Xh);
    cudaGetSymbolAddress((void**)&ch, g_Ch);
    cudaGetSymbolAddress((void**)&oh, g_Oh);
    cudaGetSymbolAddress((void**)&wh, g_Wh);

    const int proj_smem = 2 * 27648;     // 55,296 B (4 CTAs/SM = 221 KB)
    const int attn_smem = 73728;         // 73,728 B (2 CTAs/SM)
    cudaFuncSetAttribute(proj_fp16_kernel<1>,
        cudaFuncAttributeMaxDynamicSharedMemorySize, proj_smem);
    cudaFuncSetAttribute(proj_fp16_kernel<0>,
        cudaFuncAttributeMaxDynamicSharedMemorySize, proj_smem);
    cudaFuncSetAttribute(attn_kernel,
        cudaFuncAttributeMaxDynamicSharedMemorySize, attn_smem);
    cudaFuncSetAttribute(proj_fp16_kernel<1>,
        cudaFuncAttributePreferredSharedMemoryCarveout, 100);
    cudaFuncSetAttribute(proj_fp16_kernel<0>,
        cudaFuncAttributePreferredSharedMemoryCarveout, 100);
    cudaFuncSetAttribute(attn_kernel,
        cudaFuncAttributePreferredSharedMemoryCarveout, 100);

    // 1) fp32 -> fp16 conversions
    conv_all_kernel<<<12288, 256>>>(x, ctx, Wq, Wk, Wv, Wo, xh, ch, wh);

    // 2) merged Q/K/V projections (fp16 head-major out)
    ProjArgs pa;
    pa.A[0] = xh; pa.Wp[0] = wh + 0u * 1048576u; pa.bias[0] = bq; pa.out[0] = qh; pa.scale[0] = 0.125f;
    pa.A[1] = ch; pa.Wp[1] = wh + 1u * 1048576u; pa.bias[1] = bk; pa.out[1] = kh; pa.scale[1] = 1.0f;
    pa.A[2] = ch; pa.Wp[2] = wh + 2u * 1048576u; pa.bias[2] = bv; pa.out[2] = vh; pa.scale[2] = 1.0f;
    dim3 gp(16, 32, 3);
    proj_fp16_kernel<1><<<gp, 256, proj_smem>>>(pa);

    // 3) attention (fp16 mma, q-tile 128, key-tile 128, single-plane out)
    dim3 ga(N_ / 128, H_, B_);   // (16, 16, 2)
    attn_kernel<<<ga, 256, attn_smem>>>(qh, kh, vh, bias, oh);

    // 4) output projection: 1-term fp16 (f32 row-major out)
    ProjArgs po;
    po.A[0] = oh; po.Wp[0] = wh + 3u * 1048576u; po.bias[0] = bo; po.out[0] = out; po.scale[0] = 1.0f;
    po.A[1] = po.A[0]; po.Wp[1] = po.Wp[0]; po.bias[1] = po.bias[0]; po.out[1] = po.out[0]; po.scale[1] = 1.0f;
    po.A[2] = po.A[0]; po.Wp[2] = po.Wp[0]; po.bias[2] = po.bias[0]; po.out[2] = po.out[0]; po.scale[2] = 1.0f;
    dim3 go(16, 32, 1);
    proj_fp16_kernel<0><<<go, 256, proj_smem>>>(po);
}